// round 2
// baseline (speedup 1.0000x reference)
#include <cuda_runtime.h>
#include <cstddef>

#define NN 100000
#define EE 800000
#define HH 256
#define NL 6
#define LDW1 259
#define LDW2 512

// ---- scratch (device globals; no allocation anywhere) ----
__device__ __align__(16) float g_h0[(size_t)NN * HH];
__device__ __align__(16) float g_h1[(size_t)NN * HH];
__device__ __align__(16) float g_P [(size_t)NN * HH];
__device__ __align__(16) float g_hN[(size_t)NN * HH];
__device__ __align__(16) float g_deg[NN];
__device__ __align__(16) float g_inv[NN];

// ---- utility kernels ----
__global__ void zero_kernel(float4* __restrict__ p, int n4) {
    int i = blockIdx.x * blockDim.x + threadIdx.x;
    int st = gridDim.x * blockDim.x;
    float4 z = make_float4(0.f, 0.f, 0.f, 0.f);
    for (; i < n4; i += st) p[i] = z;
}

__global__ void deg_kernel(const int* __restrict__ dst, float* __restrict__ deg) {
    int i = blockIdx.x * blockDim.x + threadIdx.x;
    if (i < EE) atomicAdd(&deg[dst[i]], 1.0f);
}

__global__ void invdeg_kernel(const float* __restrict__ deg, float* __restrict__ inv) {
    int i = blockIdx.x * blockDim.x + threadIdx.x;
    if (i < NN) inv[i] = 1.0f / fmaxf(deg[i], 1.0f);
}

__global__ void init_h_kernel(const int* __restrict__ gt, const float* __restrict__ emb,
                              float* __restrict__ h) {
    int i = blockIdx.x * blockDim.x + threadIdx.x;
    int st = gridDim.x * blockDim.x;
    const int n4 = NN * HH / 4;
    const float4* e4 = (const float4*)emb;
    float4* h4 = (float4*)h;
    for (; i < n4; i += st) {
        int n = i >> 6;       // 64 float4 per row
        int j = i & 63;
        h4[i] = e4[(size_t)gt[n] * 64 + j];
    }
}

// ---- SGEMM: C[M x 256] = act( A[M x K] @ W[256 x K]^T + bias )
// A is logically [A1 | A2*invdeg] when A2 != nullptr (K=512), else A1 (K=256).
// W row-major with row stride ldw (>= K). Tile: BM=128, BN=64, BK=16, 256 thr, 8x4/thread.
__global__ __launch_bounds__(256)
void gemm_kernel(const float* __restrict__ A1, const float* __restrict__ A2,
                 const float* __restrict__ invdeg,
                 const float* __restrict__ W, int ldw, int K,
                 const float* __restrict__ bias, int do_relu,
                 float* __restrict__ C, int M) {
    __shared__ float As[16][128];
    __shared__ float Bs[16][64];
    const int t  = threadIdx.x;
    const int tx = t & 15;       // 16 cols of 4 -> 64
    const int ty = t >> 4;       // 16 rows of 8 -> 128
    const int m0 = blockIdx.x * 128;
    const int n0 = blockIdx.y * 64;

    const int ar0 = t >> 2;            // 0..63 (A rows, +64 on second load)
    const int akq = (t & 3) * 4;       // k sub-offset 0/4/8/12

    float acc[8][4];
#pragma unroll
    for (int i = 0; i < 8; i++)
#pragma unroll
        for (int j = 0; j < 4; j++) acc[i][j] = 0.f;

    for (int kt = 0; kt < K; kt += 16) {
        // ---- load A tile (2 x float4 per thread), transpose into As[k][m]
#pragma unroll
        for (int li = 0; li < 2; li++) {
            int row = ar0 + li * 64;
            int gr  = m0 + row;
            int kg  = kt + akq;
            float4 v = make_float4(0.f, 0.f, 0.f, 0.f);
            if (gr < M) {
                if (kg < 256) {
                    v = *(const float4*)&A1[(size_t)gr * HH + kg];
                } else {
                    float4 u = *(const float4*)&A2[(size_t)gr * HH + (kg - 256)];
                    float s = invdeg[gr];
                    v = make_float4(u.x * s, u.y * s, u.z * s, u.w * s);
                }
            }
            As[akq + 0][row] = v.x;
            As[akq + 1][row] = v.y;
            As[akq + 2][row] = v.z;
            As[akq + 3][row] = v.w;
        }
        // ---- load B tile (4 scalars per thread; ldw=259 breaks float4 alignment)
        {
            int brow = t >> 2;                 // 0..63
            int kb = (t & 3) * 4;
            const float* wp = &W[(size_t)(n0 + brow) * ldw + kt + kb];
#pragma unroll
            for (int i = 0; i < 4; i++) Bs[kb + i][brow] = wp[i];
        }
        __syncthreads();
#pragma unroll
        for (int k = 0; k < 16; k++) {
            float4 a0 = *(const float4*)&As[k][ty * 8];
            float4 a1 = *(const float4*)&As[k][ty * 8 + 4];
            float4 b  = *(const float4*)&Bs[k][tx * 4];
            float av[8] = {a0.x, a0.y, a0.z, a0.w, a1.x, a1.y, a1.z, a1.w};
            float bv[4] = {b.x, b.y, b.z, b.w};
#pragma unroll
            for (int i = 0; i < 8; i++)
#pragma unroll
                for (int j = 0; j < 4; j++) acc[i][j] += av[i] * bv[j];
        }
        __syncthreads();
    }
    // ---- epilogue
#pragma unroll
    for (int i = 0; i < 8; i++) {
        int gr = m0 + ty * 8 + i;
        if (gr < M) {
            float4 v = make_float4(acc[i][0], acc[i][1], acc[i][2], acc[i][3]);
            int gc = n0 + tx * 4;
            if (bias) {
                float4 bb = *(const float4*)&bias[gc];
                v.x += bb.x; v.y += bb.y; v.z += bb.z; v.w += bb.w;
            }
            if (do_relu) {
                v.x = fmaxf(v.x, 0.f); v.y = fmaxf(v.y, 0.f);
                v.z = fmaxf(v.z, 0.f); v.w = fmaxf(v.w, 0.f);
            }
            *(float4*)&C[(size_t)gr * HH + gc] = v;
        }
    }
}

// ---- edge scatter: hN[dst] += leaky_relu(P[src] + w @ W1b^T)
// one warp per edge; lane handles cols {lane*4..+3, 128+lane*4..+3}; W1b slice in regs.
__global__ __launch_bounds__(256)
void scatter_kernel(const int* __restrict__ src, const int* __restrict__ dst,
                    const float* __restrict__ w, const float* __restrict__ W1l,
                    const float* __restrict__ P, float* __restrict__ hN) {
    const int lane = threadIdx.x & 31;
    const int wid  = (blockIdx.x * blockDim.x + threadIdx.x) >> 5;
    const int nw   = (gridDim.x * blockDim.x) >> 5;

    float wb[2][4][3];
#pragma unroll
    for (int r = 0; r < 2; r++)
#pragma unroll
        for (int i = 0; i < 4; i++) {
            int j = r * 128 + lane * 4 + i;
            const float* p = &W1l[(size_t)j * LDW1 + 256];
            wb[r][i][0] = p[0]; wb[r][i][1] = p[1]; wb[r][i][2] = p[2];
        }

    for (int e = wid; e < EE; e += nw) {
        int s = src[e], d = dst[e];
        float w0 = w[(size_t)e * 3 + 0];
        float w1 = w[(size_t)e * 3 + 1];
        float w2 = w[(size_t)e * 3 + 2];
        const float4* pp = (const float4*)(P + (size_t)s * HH);
        float* op = hN + (size_t)d * HH;
#pragma unroll
        for (int r = 0; r < 2; r++) {
            int q = r * 32 + lane;           // float4 index within row
            float4 v = pp[q];
            float o[4];
            float vv[4] = {v.x, v.y, v.z, v.w};
#pragma unroll
            for (int i = 0; i < 4; i++) {
                float tt = vv[i] + w0 * wb[r][i][0] + w1 * wb[r][i][1] + w2 * wb[r][i][2];
                o[i] = tt > 0.f ? tt : 0.01f * tt;
            }
            asm volatile("red.global.add.v4.f32 [%0], {%1,%2,%3,%4};"
                         :: "l"(op + q * 4), "f"(o[0]), "f"(o[1]), "f"(o[2]), "f"(o[3])
                         : "memory");
        }
    }
}

// ---- final head: out[n] = x[n] . Wh2 + bh2 (one warp per node)
__global__ __launch_bounds__(256)
void out_kernel(const float* __restrict__ x, const float* __restrict__ Wh2,
                const float* __restrict__ bh2, float* __restrict__ out) {
    const int lane = threadIdx.x & 31;
    const int wid  = (blockIdx.x * blockDim.x + threadIdx.x) >> 5;
    const int nw   = (gridDim.x * blockDim.x) >> 5;
    float4 wr0 = *(const float4*)&Wh2[lane * 8];
    float4 wr1 = *(const float4*)&Wh2[lane * 8 + 4];
    float b = bh2[0];
    for (int n = wid; n < NN; n += nw) {
        const float4* xp = (const float4*)(x + (size_t)n * HH + lane * 8);
        float4 x0 = xp[0], x1 = xp[1];
        float s = x0.x * wr0.x + x0.y * wr0.y + x0.z * wr0.z + x0.w * wr0.w
                + x1.x * wr1.x + x1.y * wr1.y + x1.z * wr1.z + x1.w * wr1.w;
#pragma unroll
        for (int o = 16; o > 0; o >>= 1) s += __shfl_xor_sync(0xffffffffu, s, o);
        if (lane == 0) out[n] = s + b;
    }
}

extern "C" void kernel_launch(void* const* d_in, const int* in_sizes, int n_in,
                              void* d_out, int out_size) {
    const int*   gate = (const int*)d_in[0];
    const int*   src  = (const int*)d_in[1];
    const int*   dst  = (const int*)d_in[2];
    const float* w    = (const float*)d_in[3];
    const float* emb  = (const float*)d_in[4];
    const float* W1   = (const float*)d_in[5];
    const float* W2   = (const float*)d_in[6];
    const float* b2   = (const float*)d_in[7];
    const float* Wh1  = (const float*)d_in[8];
    const float* bh1  = (const float*)d_in[9];
    const float* Wh2  = (const float*)d_in[10];
    const float* bh2  = (const float*)d_in[11];
    float* out = (float*)d_out;

    float *h0, *h1, *P, *hN, *deg, *inv;
    cudaGetSymbolAddress((void**)&h0,  g_h0);
    cudaGetSymbolAddress((void**)&h1,  g_h1);
    cudaGetSymbolAddress((void**)&P,   g_P);
    cudaGetSymbolAddress((void**)&hN,  g_hN);
    cudaGetSymbolAddress((void**)&deg, g_deg);
    cudaGetSymbolAddress((void**)&inv, g_inv);

    const int T = 256;
    // degree + inv-degree (once per call)
    zero_kernel<<<128, T>>>((float4*)deg, NN / 4);
    deg_kernel<<<(EE + T - 1) / T, T>>>(dst, deg);
    invdeg_kernel<<<(NN + T - 1) / T, T>>>(deg, inv);
    // h = emb[gate_type]
    init_h_kernel<<<1184, T>>>(gate, emb, h0);

    dim3 gg((NN + 127) / 128, 4);
    float* hin = h0;
    float* hout = h1;
    for (int l = 0; l < NL; l++) {
        zero_kernel<<<2048, T>>>((float4*)hN, NN * HH / 4);
        // P = h @ W1a^T  (W1a = W1[l][:, :256])
        gemm_kernel<<<gg, 256>>>(hin, nullptr, nullptr,
                                 W1 + (size_t)l * HH * LDW1, LDW1, 256,
                                 nullptr, 0, P, NN);
        // hN[dst] += leaky_relu(P[src] + w @ W1b^T)
        scatter_kernel<<<1184, 256>>>(src, dst, w, W1 + (size_t)l * HH * LDW1, P, hN);
        // h' = relu([h | hN*invdeg] @ W2^T + b2)
        gemm_kernel<<<gg, 256>>>(hin, hN, inv,
                                 W2 + (size_t)l * HH * LDW2, LDW2, 512,
                                 b2 + (size_t)l * HH, 1, hout, NN);
        float* tp = hin; hin = hout; hout = tp;
    }
    // head: x = relu(h @ Wh1^T + bh1) ; out = x @ Wh2^T + bh2
    gemm_kernel<<<gg, 256>>>(hin, nullptr, nullptr, Wh1, HH, 256, bh1, 1, P, NN);
    out_kernel<<<1184, 256>>>(P, Wh2, bh2, out);
}

// round 5
// speedup vs baseline: 2.1210x; 2.1210x over previous
#include <cuda_runtime.h>
#include <cuda_bf16.h>
#include <cstddef>
#include <cstdint>

#define NN 100000
#define EE 800000
#define HH 256
#define NL 6
#define LDW1 259

// ---------------- scratch (device globals; no allocation anywhere) -------------
__device__ __align__(16) __nv_bfloat16 g_hA_hi[(size_t)NN * HH];
__device__ __align__(16) __nv_bfloat16 g_hA_lo[(size_t)NN * HH];
__device__ __align__(16) __nv_bfloat16 g_hB_hi[(size_t)NN * HH];
__device__ __align__(16) __nv_bfloat16 g_hB_lo[(size_t)NN * HH];
__device__ __align__(16) __nv_bfloat16 g_nh[(size_t)NN * HH];
__device__ __align__(16) __nv_bfloat16 g_nl[(size_t)NN * HH];
__device__ __align__(16) float g_P [(size_t)NN * HH];
__device__ __align__(16) float g_hN[(size_t)NN * HH];
__device__ float g_deg[NN];
__device__ float g_inv[NN];
__device__ __align__(16) __nv_bfloat16 g_w1h[NL * HH * HH],  g_w1l[NL * HH * HH];
__device__ __align__(16) __nv_bfloat16 g_w2h[NL * HH * 512], g_w2l[NL * HH * 512];
__device__ __align__(16) __nv_bfloat16 g_wh1h[HH * HH],      g_wh1l[HH * HH];

// ---------------- helpers ------------------------------------------------------
__device__ __forceinline__ uint32_t smem_u32(const void* p) {
    uint32_t a;
    asm("{ .reg .u64 t; cvta.to.shared.u64 t, %1; cvt.u32.u64 %0, t; }" : "=r"(a) : "l"(p));
    return a;
}
__device__ __forceinline__ uint32_t swz(uint32_t o) { return o ^ ((o >> 3) & 0x70); }

__device__ __forceinline__ void split_bf16(float f, unsigned short& h, unsigned short& l) {
    __nv_bfloat16 hb = __float2bfloat16_rn(f);
    __nv_bfloat16 lb = __float2bfloat16_rn(f - __bfloat162float(hb));
    h = __bfloat16_as_ushort(hb);
    l = __bfloat16_as_ushort(lb);
}
__device__ __forceinline__ void ldsm4(uint32_t* r, uint32_t addr) {
    asm volatile("ldmatrix.sync.aligned.m8n8.x4.shared.b16 {%0,%1,%2,%3}, [%4];"
                 : "=r"(r[0]), "=r"(r[1]), "=r"(r[2]), "=r"(r[3]) : "r"(addr));
}
__device__ __forceinline__ void mma16816(float* c, const uint32_t* a, uint32_t b0, uint32_t b1) {
    asm volatile("mma.sync.aligned.m16n8k16.row.col.f32.bf16.bf16.f32 "
                 "{%0,%1,%2,%3}, {%4,%5,%6,%7}, {%8,%9}, {%0,%1,%2,%3};"
                 : "+f"(c[0]), "+f"(c[1]), "+f"(c[2]), "+f"(c[3])
                 : "r"(a[0]), "r"(a[1]), "r"(a[2]), "r"(a[3]), "r"(b0), "r"(b1));
}
__device__ __forceinline__ void cp16(uint32_t dst, const void* src) {
    asm volatile("cp.async.cg.shared.global [%0], [%1], 16;" :: "r"(dst), "l"(src));
}
__device__ __forceinline__ void cp16z(uint32_t dst, const void* src, int sz) {
    asm volatile("cp.async.cg.shared.global [%0], [%1], 16, %2;" :: "r"(dst), "l"(src), "r"(sz));
}
__device__ __forceinline__ void cp_commit() {
    asm volatile("cp.async.commit_group;" ::: "memory");
}
template <int N> __device__ __forceinline__ void cp_wait() {
    asm volatile("cp.async.wait_group %0;" :: "n"(N) : "memory");
}

// ---------------- small utility kernels ---------------------------------------
__global__ void zero_kernel(float4* __restrict__ p, int n4) {
    int i = blockIdx.x * blockDim.x + threadIdx.x;
    int st = gridDim.x * blockDim.x;
    float4 z = make_float4(0.f, 0.f, 0.f, 0.f);
    for (; i < n4; i += st) p[i] = z;
}
__global__ void deg_kernel(const int* __restrict__ dst, float* __restrict__ deg) {
    int i = blockIdx.x * blockDim.x + threadIdx.x;
    if (i < EE) atomicAdd(&deg[dst[i]], 1.0f);
}
__global__ void invdeg_kernel(const float* __restrict__ deg, float* __restrict__ inv) {
    int i = blockIdx.x * blockDim.x + threadIdx.x;
    if (i < NN) inv[i] = 1.0f / fmaxf(deg[i], 1.0f);
}
__global__ void convw_kernel(const float* __restrict__ src, int ld, int n, int cols,
                             __nv_bfloat16* __restrict__ hi, __nv_bfloat16* __restrict__ lo) {
    int i = blockIdx.x * blockDim.x + threadIdx.x;
    int st = gridDim.x * blockDim.x;
    for (; i < n; i += st) {
        int r = i / cols, c = i - r * cols;
        float v = src[(size_t)r * ld + c];
        unsigned short h, l;
        split_bf16(v, h, l);
        hi[i] = __ushort_as_bfloat16(h);
        lo[i] = __ushort_as_bfloat16(l);
    }
}
__global__ void init_h2_kernel(const int* __restrict__ gt, const float* __restrict__ emb,
                               __nv_bfloat16* __restrict__ hi, __nv_bfloat16* __restrict__ lo) {
    int i = blockIdx.x * blockDim.x + threadIdx.x;
    int st = gridDim.x * blockDim.x;
    const int n = NN * HH;
    for (; i < n; i += st) {
        int nd = i >> 8, c = i & 255;
        float v = emb[(size_t)gt[nd] * HH + c];
        unsigned short h, l;
        split_bf16(v, h, l);
        hi[i] = __ushort_as_bfloat16(h);
        lo[i] = __ushort_as_bfloat16(l);
    }
}
// hN (fp32) * inv[node] -> bf16 hi/lo pair
__global__ void convhN_kernel(const float* __restrict__ hN, const float* __restrict__ inv,
                              __nv_bfloat16* __restrict__ hi, __nv_bfloat16* __restrict__ lo) {
    int i = blockIdx.x * blockDim.x + threadIdx.x;
    int st = gridDim.x * blockDim.x;
    const int n4 = NN * HH / 4;
    const float4* src = (const float4*)hN;
    for (; i < n4; i += st) {
        int nd = i >> 6;
        float s = inv[nd];
        float4 v = src[i];
        float f[4] = {v.x * s, v.y * s, v.z * s, v.w * s};
        unsigned short h[4], l[4];
#pragma unroll
        for (int j = 0; j < 4; j++) split_bf16(f[j], h[j], l[j]);
        uint2 ph = make_uint2((uint32_t)h[0] | ((uint32_t)h[1] << 16),
                              (uint32_t)h[2] | ((uint32_t)h[3] << 16));
        uint2 pl = make_uint2((uint32_t)l[0] | ((uint32_t)l[1] << 16),
                              (uint32_t)l[2] | ((uint32_t)l[3] << 16));
        *(uint2*)(hi + (size_t)i * 4) = ph;
        *(uint2*)(lo + (size_t)i * 4) = pl;
    }
}

// ---------------- mma.sync GEMM ------------------------------------------------
// C[M x 256] = act( A[M x K] @ B[256 x K]^T (+bias) )
// A: bf16 hi/lo pairs; chunks k<256 from (aH1,aL1), k>=256 from (aH2,aL2).
// B: bf16 hi/lo pairs [256 x K] row-major.
// bf16x3: C = Ah*Bh + Ah*Bl + Al*Bh, fp32 accumulate.
// mode: 0 = fp32 out; 1 = bias+relu -> bf16 hi/lo pair; 2 = bias+relu -> fp32.
// CTA: 128x128, BK=64, 8 warps (4 M x 2 N), warp tile 32x64.
// SMEM per stage (64KB): Ahi(16K) Alo(16K) Bhi(16K) Blo(16K); 2 stages.
#define GEMM_SMEM 131072

__global__ __launch_bounds__(256, 1)
void mma_gemm(const __nv_bfloat16* __restrict__ aH1, const __nv_bfloat16* __restrict__ aL1,
              const __nv_bfloat16* __restrict__ aH2, const __nv_bfloat16* __restrict__ aL2,
              const __nv_bfloat16* __restrict__ bH, const __nv_bfloat16* __restrict__ bL,
              int K, const float* __restrict__ bias, int mode,
              float* __restrict__ outF, __nv_bfloat16* __restrict__ oH,
              __nv_bfloat16* __restrict__ oL, int M) {
    extern __shared__ char smem[];
    const uint32_t sbase = smem_u32(smem);
    const int t = threadIdx.x;
    const int m0 = blockIdx.x * 128;
    const int n0 = blockIdx.y * 128;
    const int C = K >> 6;
    const int w = t >> 5, lane = t & 31;
    const int wm = w & 3, wn = w >> 2;

    float acc[2][8][4];
#pragma unroll
    for (int a = 0; a < 2; a++)
#pragma unroll
        for (int b = 0; b < 8; b++)
#pragma unroll
            for (int c = 0; c < 4; c++) acc[a][b][c] = 0.f;

    auto issue_stage = [&](int c) {
        const uint32_t st = sbase + (uint32_t)(c & 1) * 65536u;
        const int kc = c << 6;
        const __nv_bfloat16* AH = (kc < 256) ? aH1 : aH2;
        const __nv_bfloat16* AL = (kc < 256) ? aL1 : aL2;
        const int ko = kc & 255;
        // A: 2048 x 16B (hi then lo)
        for (int s = t; s < 2048; s += 256) {
            int which = s >> 10, ss = s & 1023;
            int r = ss >> 3, c8 = ss & 7;
            int gr = m0 + r;
            int grc = gr < M ? gr : (M - 1);
            const __nv_bfloat16* gp = (which ? AL : AH) + ((size_t)grc * HH + ko + c8 * 8);
            uint32_t dst = st + (uint32_t)which * 16384u + swz((uint32_t)(r * 128 + c8 * 16));
            cp16z(dst, gp, gr < M ? 16 : 0);
        }
        // B: 2048 x 16B (hi then lo)
        for (int s = t; s < 2048; s += 256) {
            int which = s >> 10, ss = s & 1023;
            int n = ss >> 3, c8 = ss & 7;
            const __nv_bfloat16* gp = (which ? bL : bH) + ((size_t)(n0 + n) * K + kc + c8 * 8);
            uint32_t dst = st + 32768u + (uint32_t)which * 16384u + swz((uint32_t)(n * 128 + c8 * 16));
            cp16(dst, gp);
        }
    };

    auto compute = [&](int b) {
        const uint32_t Ab = sbase + (uint32_t)b * 65536u;
        const uint32_t Bb = Ab + 32768u;
        const int sub = lane >> 3, rr = lane & 7;
#pragma unroll
        for (int ks = 0; ks < 4; ks++) {
            const int kb = ks * 32;     // byte offset of k16 step
            uint32_t Ah[2][4], Al[2][4];
#pragma unroll
            for (int mt = 0; mt < 2; mt++) {
                int row = wm * 32 + mt * 16 + (sub & 1) * 8 + rr;
                uint32_t off = swz((uint32_t)(row * 128 + kb + (sub >> 1) * 16));
                ldsm4(Ah[mt], Ab + off);
                ldsm4(Al[mt], Ab + 16384u + off);
            }
#pragma unroll
            for (int np = 0; np < 4; np++) {
                int nrow = wn * 64 + np * 16 + (sub >> 1) * 8 + rr;
                uint32_t off = swz((uint32_t)(nrow * 128 + kb + (sub & 1) * 16));
                uint32_t Bh[4], Bl[4];
                ldsm4(Bh, Bb + off);
                ldsm4(Bl, Bb + 16384u + off);
#pragma unroll
                for (int mt = 0; mt < 2; mt++) {
                    mma16816(acc[mt][2 * np],     Ah[mt], Bh[0], Bh[1]);
                    mma16816(acc[mt][2 * np],     Ah[mt], Bl[0], Bl[1]);
                    mma16816(acc[mt][2 * np],     Al[mt], Bh[0], Bh[1]);
                    mma16816(acc[mt][2 * np + 1], Ah[mt], Bh[2], Bh[3]);
                    mma16816(acc[mt][2 * np + 1], Ah[mt], Bl[2], Bl[3]);
                    mma16816(acc[mt][2 * np + 1], Al[mt], Bh[2], Bh[3]);
                }
            }
        }
    };

    issue_stage(0);
    cp_commit();
    for (int c = 0; c < C; c++) {
        if (c + 1 < C) { issue_stage(c + 1); cp_commit(); }
        if (c + 1 < C) cp_wait<1>(); else cp_wait<0>();
        __syncthreads();
        compute(c & 1);
        __syncthreads();
    }

    // ---- epilogue
    const int q = lane >> 2;
    const int r2 = (lane & 3) * 2;
#pragma unroll
    for (int mt = 0; mt < 2; mt++) {
        int row0 = m0 + wm * 32 + mt * 16 + q;
#pragma unroll
        for (int half = 0; half < 2; half++) {
            int row = row0 + half * 8;
            if (row >= M) continue;
#pragma unroll
            for (int nt = 0; nt < 8; nt++) {
                int gc = n0 + wn * 64 + nt * 8 + r2;
                float v0 = acc[mt][nt][half * 2 + 0];
                float v1 = acc[mt][nt][half * 2 + 1];
                if (mode) {
                    v0 = fmaxf(v0 + __ldg(&bias[gc]), 0.f);
                    v1 = fmaxf(v1 + __ldg(&bias[gc + 1]), 0.f);
                }
                if (mode == 1) {
                    unsigned short h0, l0, h1, l1;
                    split_bf16(v0, h0, l0);
                    split_bf16(v1, h1, l1);
                    *(uint32_t*)(oH + (size_t)row * HH + gc) = (uint32_t)h0 | ((uint32_t)h1 << 16);
                    *(uint32_t*)(oL + (size_t)row * HH + gc) = (uint32_t)l0 | ((uint32_t)l1 << 16);
                } else {
                    *(float2*)(outF + (size_t)row * HH + gc) = make_float2(v0, v1);
                }
            }
        }
    }
}

// ---------------- edge scatter: hN[dst] += leaky_relu(P[src] + w @ W1b^T) ------
__global__ __launch_bounds__(256)
void scatter_kernel(const int* __restrict__ src, const int* __restrict__ dst,
                    const float* __restrict__ w, const float* __restrict__ W1l,
                    const float* __restrict__ P, float* __restrict__ hN) {
    const int lane = threadIdx.x & 31;
    const int wid = (blockIdx.x * blockDim.x + threadIdx.x) >> 5;
    const int nw = (gridDim.x * blockDim.x) >> 5;

    float wb[2][4][3];
#pragma unroll
    for (int r = 0; r < 2; r++)
#pragma unroll
        for (int i = 0; i < 4; i++) {
            int j = r * 128 + lane * 4 + i;
            const float* p = &W1l[(size_t)j * LDW1 + 256];
            wb[r][i][0] = p[0]; wb[r][i][1] = p[1]; wb[r][i][2] = p[2];
        }
    for (int e = wid; e < EE; e += nw) {
        int s = src[e], d = dst[e];
        float w0 = w[(size_t)e * 3 + 0];
        float w1 = w[(size_t)e * 3 + 1];
        float w2 = w[(size_t)e * 3 + 2];
        const float4* pp = (const float4*)(P + (size_t)s * HH);
        float* op = hN + (size_t)d * HH;
#pragma unroll
        for (int r = 0; r < 2; r++) {
            int qq = r * 32 + lane;
            float4 v = pp[qq];
            float vv[4] = {v.x, v.y, v.z, v.w};
            float o[4];
#pragma unroll
            for (int i = 0; i < 4; i++) {
                float tt = vv[i] + w0 * wb[r][i][0] + w1 * wb[r][i][1] + w2 * wb[r][i][2];
                o[i] = tt > 0.f ? tt : 0.01f * tt;
            }
            asm volatile("red.global.add.v4.f32 [%0], {%1,%2,%3,%4};"
                         :: "l"(op + qq * 4), "f"(o[0]), "f"(o[1]), "f"(o[2]), "f"(o[3])
                         : "memory");
        }
    }
}

// ---------------- final head dot -----------------------------------------------
__global__ __launch_bounds__(256)
void out_kernel(const float* __restrict__ x, const float* __restrict__ Wh2,
                const float* __restrict__ bh2, float* __restrict__ out) {
    const int lane = threadIdx.x & 31;
    const int wid = (blockIdx.x * blockDim.x + threadIdx.x) >> 5;
    const int nw = (gridDim.x * blockDim.x) >> 5;
    float4 wr0 = *(const float4*)&Wh2[lane * 8];
    float4 wr1 = *(const float4*)&Wh2[lane * 8 + 4];
    float b = bh2[0];
    for (int n = wid; n < NN; n += nw) {
        const float4* xp = (const float4*)(x + (size_t)n * HH + lane * 8);
        float4 x0 = xp[0], x1 = xp[1];
        float s = x0.x * wr0.x + x0.y * wr0.y + x0.z * wr0.z + x0.w * wr0.w
                + x1.x * wr1.x + x1.y * wr1.y + x1.z * wr1.z + x1.w * wr1.w;
#pragma unroll
        for (int o = 16; o > 0; o >>= 1) s += __shfl_xor_sync(0xffffffffu, s, o);
        if (lane == 0) out[n] = s + b;
    }
}

// ---------------- launcher ------------------------------------------------------
extern "C" void kernel_launch(void* const* d_in, const int* in_sizes, int n_in,
                              void* d_out, int out_size) {
    const int*   gate = (const int*)d_in[0];
    const int*   src  = (const int*)d_in[1];
    const int*   dst  = (const int*)d_in[2];
    const float* w    = (const float*)d_in[3];
    const float* emb  = (const float*)d_in[4];
    const float* W1   = (const float*)d_in[5];
    const float* W2   = (const float*)d_in[6];
    const float* b2   = (const float*)d_in[7];
    const float* Wh1  = (const float*)d_in[8];
    const float* bh1  = (const float*)d_in[9];
    const float* Wh2  = (const float*)d_in[10];
    const float* bh2  = (const float*)d_in[11];
    float* out = (float*)d_out;

    __nv_bfloat16 *hAh, *hAl, *hBh, *hBl, *nh, *nl;
    __nv_bfloat16 *w1h, *w1l, *w2h, *w2l, *wh1h, *wh1l;
    float *P, *hN, *deg, *inv;
    cudaGetSymbolAddress((void**)&hAh, g_hA_hi);
    cudaGetSymbolAddress((void**)&hAl, g_hA_lo);
    cudaGetSymbolAddress((void**)&hBh, g_hB_hi);
    cudaGetSymbolAddress((void**)&hBl, g_hB_lo);
    cudaGetSymbolAddress((void**)&nh,  g_nh);
    cudaGetSymbolAddress((void**)&nl,  g_nl);
    cudaGetSymbolAddress((void**)&P,   g_P);
    cudaGetSymbolAddress((void**)&hN,  g_hN);
    cudaGetSymbolAddress((void**)&deg, g_deg);
    cudaGetSymbolAddress((void**)&inv, g_inv);
    cudaGetSymbolAddress((void**)&w1h, g_w1h);
    cudaGetSymbolAddress((void**)&w1l, g_w1l);
    cudaGetSymbolAddress((void**)&w2h, g_w2h);
    cudaGetSymbolAddress((void**)&w2l, g_w2l);
    cudaGetSymbolAddress((void**)&wh1h, g_wh1h);
    cudaGetSymbolAddress((void**)&wh1l, g_wh1l);

    cudaFuncSetAttribute(mma_gemm, cudaFuncAttributeMaxDynamicSharedMemorySize, GEMM_SMEM);

    const int T = 256;
    for (int l = 0; l < NL; l++) {
        convw_kernel<<<64, T>>>(W1 + (size_t)l * HH * LDW1, LDW1, HH * HH, HH,
                                w1h + (size_t)l * HH * HH, w1l + (size_t)l * HH * HH);
        convw_kernel<<<128, T>>>(W2 + (size_t)l * HH * 512, 512, HH * 512, 512,
                                 w2h + (size_t)l * HH * 512, w2l + (size_t)l * HH * 512);
    }
    convw_kernel<<<64, T>>>(Wh1, HH, HH * HH, HH, wh1h, wh1l);

    zero_kernel<<<128, T>>>((float4*)deg, NN / 4);
    deg_kernel<<<(EE + T - 1) / T, T>>>(dst, deg);
    invdeg_kernel<<<(NN + T - 1) / T, T>>>(deg, inv);
    init_h2_kernel<<<2048, T>>>(gate, emb, hAh, hAl);

    dim3 gg((NN + 127) / 128, 2);
    __nv_bfloat16 *ih = hAh, *il = hAl, *oh = hBh, *ol = hBl;
    for (int l = 0; l < NL; l++) {
        zero_kernel<<<2048, T>>>((float4*)hN, NN * HH / 4);
        // P = h @ W1a^T (fp32, no act)
        mma_gemm<<<gg, 256, GEMM_SMEM>>>(ih, il, nullptr, nullptr,
                                         w1h + (size_t)l * HH * HH, w1l + (size_t)l * HH * HH,
                                         256, nullptr, 0, P, nullptr, nullptr, NN);
        // hN[dst] += leaky_relu(P[src] + w @ W1b^T)
        scatter_kernel<<<1184, 256>>>(src, dst, w, W1 + (size_t)l * HH * LDW1, P, hN);
        // (hN * inv) -> bf16 hi/lo
        convhN_kernel<<<2048, T>>>(hN, inv, nh, nl);
        // h' = relu([h | hN*inv] @ W2^T + b2) -> bf16 pair (ping-pong)
        mma_gemm<<<gg, 256, GEMM_SMEM>>>(ih, il, nh, nl,
                                         w2h + (size_t)l * HH * 512, w2l + (size_t)l * HH * 512,
                                         512, b2 + (size_t)l * HH, 1, nullptr, oh, ol, NN);
        __nv_bfloat16* tp;
        tp = ih; ih = oh; oh = tp;
        tp = il; il = ol; ol = tp;
    }
    // head: x = relu(h @ Wh1^T + bh1) -> P (fp32); out = x @ Wh2^T + bh2
    mma_gemm<<<gg, 256, GEMM_SMEM>>>(ih, il, nullptr, nullptr, wh1h, wh1l,
                                     256, bh1, 2, P, nullptr, nullptr, NN);
    out_kernel<<<1184, 256>>>(P, Wh2, bh2, out);
}

// round 6
// speedup vs baseline: 2.5434x; 1.1992x over previous
#include <cuda_runtime.h>
#include <cuda_bf16.h>
#include <cstddef>
#include <cstdint>

#define NN 100000
#define EE 800000
#define HH 256
#define NL 6
#define LDW1 259

// ---------------- scratch (device globals; no allocation anywhere) -------------
__device__ __align__(16) __nv_bfloat16 g_hA_hi[(size_t)NN * HH];
__device__ __align__(16) __nv_bfloat16 g_hA_lo[(size_t)NN * HH];
__device__ __align__(16) __nv_bfloat16 g_hB_hi[(size_t)NN * HH];
__device__ __align__(16) __nv_bfloat16 g_hB_lo[(size_t)NN * HH];
__device__ __align__(16) __nv_bfloat16 g_nh[(size_t)NN * HH];
__device__ __align__(16) __nv_bfloat16 g_nl[(size_t)NN * HH];
__device__ __align__(16) float g_P [(size_t)NN * HH];
__device__ float g_inv[NN];
__device__ int   g_degi[NN];
__device__ int   g_rowptr[NN];
__device__ int   g_cursor[NN];
__device__ __align__(16) float4 g_erec[EE];
__device__ __align__(16) __nv_bfloat16 g_w1h[NL * HH * HH],  g_w1l[NL * HH * HH];
__device__ __align__(16) __nv_bfloat16 g_w2h[NL * HH * 512], g_w2l[NL * HH * 512];
__device__ __align__(16) __nv_bfloat16 g_wh1h[HH * HH],      g_wh1l[HH * HH];

// ---------------- helpers ------------------------------------------------------
__device__ __forceinline__ uint32_t smem_u32(const void* p) {
    uint32_t a;
    asm("{ .reg .u64 t; cvta.to.shared.u64 t, %1; cvt.u32.u64 %0, t; }" : "=r"(a) : "l"(p));
    return a;
}
__device__ __forceinline__ uint32_t swz(uint32_t o) { return o ^ ((o >> 3) & 0x70); }

__device__ __forceinline__ void split_bf16(float f, unsigned short& h, unsigned short& l) {
    __nv_bfloat16 hb = __float2bfloat16_rn(f);
    __nv_bfloat16 lb = __float2bfloat16_rn(f - __bfloat162float(hb));
    h = __bfloat16_as_ushort(hb);
    l = __bfloat16_as_ushort(lb);
}
__device__ __forceinline__ void ldsm4(uint32_t* r, uint32_t addr) {
    asm volatile("ldmatrix.sync.aligned.m8n8.x4.shared.b16 {%0,%1,%2,%3}, [%4];"
                 : "=r"(r[0]), "=r"(r[1]), "=r"(r[2]), "=r"(r[3]) : "r"(addr));
}
__device__ __forceinline__ void mma16816(float* c, const uint32_t* a, uint32_t b0, uint32_t b1) {
    asm volatile("mma.sync.aligned.m16n8k16.row.col.f32.bf16.bf16.f32 "
                 "{%0,%1,%2,%3}, {%4,%5,%6,%7}, {%8,%9}, {%0,%1,%2,%3};"
                 : "+f"(c[0]), "+f"(c[1]), "+f"(c[2]), "+f"(c[3])
                 : "r"(a[0]), "r"(a[1]), "r"(a[2]), "r"(a[3]), "r"(b0), "r"(b1));
}
__device__ __forceinline__ void cp16(uint32_t dst, const void* src) {
    asm volatile("cp.async.cg.shared.global [%0], [%1], 16;" :: "r"(dst), "l"(src));
}
__device__ __forceinline__ void cp16z(uint32_t dst, const void* src, int sz) {
    asm volatile("cp.async.cg.shared.global [%0], [%1], 16, %2;" :: "r"(dst), "l"(src), "r"(sz));
}
__device__ __forceinline__ void cp_commit() {
    asm volatile("cp.async.commit_group;" ::: "memory");
}
template <int N> __device__ __forceinline__ void cp_wait() {
    asm volatile("cp.async.wait_group %0;" :: "n"(N) : "memory");
}

// ---------------- utility / CSR-build kernels ----------------------------------
__global__ void zero_kernel(float4* __restrict__ p, int n4) {
    int i = blockIdx.x * blockDim.x + threadIdx.x;
    int st = gridDim.x * blockDim.x;
    float4 z = make_float4(0.f, 0.f, 0.f, 0.f);
    for (; i < n4; i += st) p[i] = z;
}
__global__ void hist_kernel(const int* __restrict__ dst, int* __restrict__ degi) {
    int i = blockIdx.x * blockDim.x + threadIdx.x;
    if (i < EE) atomicAdd(&degi[dst[i]], 1);
}
// single-block exclusive scan: rowptr/cursor = prefix(degi); inv = 1/max(deg,1)
__global__ __launch_bounds__(1024)
void scan_kernel(const int* __restrict__ degi, int* __restrict__ rowptr,
                 int* __restrict__ cursor, float* __restrict__ inv) {
    __shared__ int part[1024];
    const int t = threadIdx.x;
    const int CH = (NN + 1023) / 1024;
    const int start = t * CH;
    int s = 0;
    for (int i = 0; i < CH; i++) {
        int idx = start + i;
        if (idx < NN) s += degi[idx];
    }
    part[t] = s;
    __syncthreads();
    for (int off = 1; off < 1024; off <<= 1) {
        int v = part[t];
        int u = (t >= off) ? part[t - off] : 0;
        __syncthreads();
        part[t] = v + u;
        __syncthreads();
    }
    int base = (t == 0) ? 0 : part[t - 1];
    for (int i = 0; i < CH; i++) {
        int idx = start + i;
        if (idx < NN) {
            rowptr[idx] = base;
            cursor[idx] = base;
            inv[idx] = 1.0f / fmaxf((float)degi[idx], 1.0f);
            base += degi[idx];
        }
    }
}
__global__ void fill_kernel(const int* __restrict__ src, const int* __restrict__ dst,
                            const float* __restrict__ w, int* __restrict__ cursor,
                            float4* __restrict__ erec) {
    int i = blockIdx.x * blockDim.x + threadIdx.x;
    if (i < EE) {
        int pos = atomicAdd(&cursor[dst[i]], 1);
        erec[pos] = make_float4(__int_as_float(src[i]),
                                w[(size_t)i * 3 + 0], w[(size_t)i * 3 + 1], w[(size_t)i * 3 + 2]);
    }
}
__global__ void convw_kernel(const float* __restrict__ src, int ld, int n, int cols,
                             __nv_bfloat16* __restrict__ hi, __nv_bfloat16* __restrict__ lo) {
    int i = blockIdx.x * blockDim.x + threadIdx.x;
    int st = gridDim.x * blockDim.x;
    for (; i < n; i += st) {
        int r = i / cols, c = i - r * cols;
        float v = src[(size_t)r * ld + c];
        unsigned short h, l;
        split_bf16(v, h, l);
        hi[i] = __ushort_as_bfloat16(h);
        lo[i] = __ushort_as_bfloat16(l);
    }
}
__global__ void init_h2_kernel(const int* __restrict__ gt, const float* __restrict__ emb,
                               __nv_bfloat16* __restrict__ hi, __nv_bfloat16* __restrict__ lo) {
    int i = blockIdx.x * blockDim.x + threadIdx.x;
    int st = gridDim.x * blockDim.x;
    const int n = NN * HH;
    for (; i < n; i += st) {
        int nd = i >> 8, c = i & 255;
        float v = emb[(size_t)gt[nd] * HH + c];
        unsigned short h, l;
        split_bf16(v, h, l);
        hi[i] = __ushort_as_bfloat16(h);
        lo[i] = __ushort_as_bfloat16(l);
    }
}

// ---------------- CSR gather: hN = mean over in-edges of leaky(P[src] + w@W1b^T)
// warp per node; lane owns 8 INTER columns; output directly as bf16 hi/lo pair.
__global__ __launch_bounds__(256)
void gather_kernel(const int* __restrict__ rowptr, const int* __restrict__ degi,
                   const float4* __restrict__ erec, const float* __restrict__ W1f,
                   const float* __restrict__ P, const float* __restrict__ inv,
                   __nv_bfloat16* __restrict__ nh, __nv_bfloat16* __restrict__ nl) {
    const int lane = threadIdx.x & 31;
    const int wid = (blockIdx.x * blockDim.x + threadIdx.x) >> 5;
    const int nw = (gridDim.x * blockDim.x) >> 5;

    float wb[8][3];
#pragma unroll
    for (int j = 0; j < 8; j++) {
        const float* p = &W1f[(size_t)(lane * 8 + j) * LDW1 + 256];
        wb[j][0] = p[0]; wb[j][1] = p[1]; wb[j][2] = p[2];
    }
    for (int n = wid; n < NN; n += nw) {
        const int beg = rowptr[n];
        const int cnt = degi[n];
        float acc[8] = {0.f, 0.f, 0.f, 0.f, 0.f, 0.f, 0.f, 0.f};
        for (int e = 0; e < cnt; e++) {
            float4 r = __ldg(&erec[beg + e]);
            int s = __float_as_int(r.x);
            const float4* pp = (const float4*)(P + (size_t)s * HH + lane * 8);
            float4 p0 = pp[0], p1 = pp[1];
            float pv[8] = {p0.x, p0.y, p0.z, p0.w, p1.x, p1.y, p1.z, p1.w};
#pragma unroll
            for (int j = 0; j < 8; j++) {
                float t = pv[j] + r.y * wb[j][0] + r.z * wb[j][1] + r.w * wb[j][2];
                acc[j] += (t > 0.f) ? t : 0.01f * t;
            }
        }
        const float sc = inv[n];
        unsigned short hs[8], ls[8];
#pragma unroll
        for (int j = 0; j < 8; j++) split_bf16(acc[j] * sc, hs[j], ls[j]);
        uint4 vh = make_uint4((uint32_t)hs[0] | ((uint32_t)hs[1] << 16),
                              (uint32_t)hs[2] | ((uint32_t)hs[3] << 16),
                              (uint32_t)hs[4] | ((uint32_t)hs[5] << 16),
                              (uint32_t)hs[6] | ((uint32_t)hs[7] << 16));
        uint4 vl = make_uint4((uint32_t)ls[0] | ((uint32_t)ls[1] << 16),
                              (uint32_t)ls[2] | ((uint32_t)ls[3] << 16),
                              (uint32_t)ls[4] | ((uint32_t)ls[5] << 16),
                              (uint32_t)ls[6] | ((uint32_t)ls[7] << 16));
        *(uint4*)(nh + (size_t)n * HH + lane * 8) = vh;
        *(uint4*)(nl + (size_t)n * HH + lane * 8) = vl;
    }
}

// ---------------- mma.sync GEMM (unchanged from R5) ----------------------------
#define GEMM_SMEM 131072

__global__ __launch_bounds__(256, 1)
void mma_gemm(const __nv_bfloat16* __restrict__ aH1, const __nv_bfloat16* __restrict__ aL1,
              const __nv_bfloat16* __restrict__ aH2, const __nv_bfloat16* __restrict__ aL2,
              const __nv_bfloat16* __restrict__ bH, const __nv_bfloat16* __restrict__ bL,
              int K, const float* __restrict__ bias, int mode,
              float* __restrict__ outF, __nv_bfloat16* __restrict__ oH,
              __nv_bfloat16* __restrict__ oL, int M) {
    extern __shared__ char smem[];
    const uint32_t sbase = smem_u32(smem);
    const int t = threadIdx.x;
    const int m0 = blockIdx.x * 128;
    const int n0 = blockIdx.y * 128;
    const int C = K >> 6;
    const int w = t >> 5, lane = t & 31;
    const int wm = w & 3, wn = w >> 2;

    float acc[2][8][4];
#pragma unroll
    for (int a = 0; a < 2; a++)
#pragma unroll
        for (int b = 0; b < 8; b++)
#pragma unroll
            for (int c = 0; c < 4; c++) acc[a][b][c] = 0.f;

    auto issue_stage = [&](int c) {
        const uint32_t st = sbase + (uint32_t)(c & 1) * 65536u;
        const int kc = c << 6;
        const __nv_bfloat16* AH = (kc < 256) ? aH1 : aH2;
        const __nv_bfloat16* AL = (kc < 256) ? aL1 : aL2;
        const int ko = kc & 255;
        for (int s = t; s < 2048; s += 256) {
            int which = s >> 10, ss = s & 1023;
            int r = ss >> 3, c8 = ss & 7;
            int gr = m0 + r;
            int grc = gr < M ? gr : (M - 1);
            const __nv_bfloat16* gp = (which ? AL : AH) + ((size_t)grc * HH + ko + c8 * 8);
            uint32_t dst = st + (uint32_t)which * 16384u + swz((uint32_t)(r * 128 + c8 * 16));
            cp16z(dst, gp, gr < M ? 16 : 0);
        }
        for (int s = t; s < 2048; s += 256) {
            int which = s >> 10, ss = s & 1023;
            int n = ss >> 3, c8 = ss & 7;
            const __nv_bfloat16* gp = (which ? bL : bH) + ((size_t)(n0 + n) * K + kc + c8 * 8);
            uint32_t dst = st + 32768u + (uint32_t)which * 16384u + swz((uint32_t)(n * 128 + c8 * 16));
            cp16(dst, gp);
        }
    };

    auto compute = [&](int b) {
        const uint32_t Ab = sbase + (uint32_t)b * 65536u;
        const uint32_t Bb = Ab + 32768u;
        const int sub = lane >> 3, rr = lane & 7;
#pragma unroll
        for (int ks = 0; ks < 4; ks++) {
            const int kb = ks * 32;
            uint32_t Ah[2][4], Al[2][4];
#pragma unroll
            for (int mt = 0; mt < 2; mt++) {
                int row = wm * 32 + mt * 16 + (sub & 1) * 8 + rr;
                uint32_t off = swz((uint32_t)(row * 128 + kb + (sub >> 1) * 16));
                ldsm4(Ah[mt], Ab + off);
                ldsm4(Al[mt], Ab + 16384u + off);
            }
#pragma unroll
            for (int np = 0; np < 4; np++) {
                int nrow = wn * 64 + np * 16 + (sub >> 1) * 8 + rr;
                uint32_t off = swz((uint32_t)(nrow * 128 + kb + (sub & 1) * 16));
                uint32_t Bh[4], Bl[4];
                ldsm4(Bh, Bb + off);
                ldsm4(Bl, Bb + 16384u + off);
#pragma unroll
                for (int mt = 0; mt < 2; mt++) {
                    mma16816(acc[mt][2 * np],     Ah[mt], Bh[0], Bh[1]);
                    mma16816(acc[mt][2 * np],     Ah[mt], Bl[0], Bl[1]);
                    mma16816(acc[mt][2 * np],     Al[mt], Bh[0], Bh[1]);
                    mma16816(acc[mt][2 * np + 1], Ah[mt], Bh[2], Bh[3]);
                    mma16816(acc[mt][2 * np + 1], Ah[mt], Bl[2], Bl[3]);
                    mma16816(acc[mt][2 * np + 1], Al[mt], Bh[2], Bh[3]);
                }
            }
        }
    };

    issue_stage(0);
    cp_commit();
    for (int c = 0; c < C; c++) {
        if (c + 1 < C) { issue_stage(c + 1); cp_commit(); }
        if (c + 1 < C) cp_wait<1>(); else cp_wait<0>();
        __syncthreads();
        compute(c & 1);
        __syncthreads();
    }

    const int q = lane >> 2;
    const int r2 = (lane & 3) * 2;
#pragma unroll
    for (int mt = 0; mt < 2; mt++) {
        int row0 = m0 + wm * 32 + mt * 16 + q;
#pragma unroll
        for (int half = 0; half < 2; half++) {
            int row = row0 + half * 8;
            if (row >= M) continue;
#pragma unroll
            for (int nt = 0; nt < 8; nt++) {
                int gc = n0 + wn * 64 + nt * 8 + r2;
                float v0 = acc[mt][nt][half * 2 + 0];
                float v1 = acc[mt][nt][half * 2 + 1];
                if (mode) {
                    v0 = fmaxf(v0 + __ldg(&bias[gc]), 0.f);
                    v1 = fmaxf(v1 + __ldg(&bias[gc + 1]), 0.f);
                }
                if (mode == 1) {
                    unsigned short h0, l0, h1, l1;
                    split_bf16(v0, h0, l0);
                    split_bf16(v1, h1, l1);
                    *(uint32_t*)(oH + (size_t)row * HH + gc) = (uint32_t)h0 | ((uint32_t)h1 << 16);
                    *(uint32_t*)(oL + (size_t)row * HH + gc) = (uint32_t)l0 | ((uint32_t)l1 << 16);
                } else {
                    *(float2*)(outF + (size_t)row * HH + gc) = make_float2(v0, v1);
                }
            }
        }
    }
}

// ---------------- final head dot -----------------------------------------------
__global__ __launch_bounds__(256)
void out_kernel(const float* __restrict__ x, const float* __restrict__ Wh2,
                const float* __restrict__ bh2, float* __restrict__ out) {
    const int lane = threadIdx.x & 31;
    const int wid = (blockIdx.x * blockDim.x + threadIdx.x) >> 5;
    const int nw = (gridDim.x * blockDim.x) >> 5;
    float4 wr0 = *(const float4*)&Wh2[lane * 8];
    float4 wr1 = *(const float4*)&Wh2[lane * 8 + 4];
    float b = bh2[0];
    for (int n = wid; n < NN; n += nw) {
        const float4* xp = (const float4*)(x + (size_t)n * HH + lane * 8);
        float4 x0 = xp[0], x1 = xp[1];
        float s = x0.x * wr0.x + x0.y * wr0.y + x0.z * wr0.z + x0.w * wr0.w
                + x1.x * wr1.x + x1.y * wr1.y + x1.z * wr1.z + x1.w * wr1.w;
#pragma unroll
        for (int o = 16; o > 0; o >>= 1) s += __shfl_xor_sync(0xffffffffu, s, o);
        if (lane == 0) out[n] = s + b;
    }
}

// ---------------- launcher ------------------------------------------------------
extern "C" void kernel_launch(void* const* d_in, const int* in_sizes, int n_in,
                              void* d_out, int out_size) {
    const int*   gate = (const int*)d_in[0];
    const int*   src  = (const int*)d_in[1];
    const int*   dst  = (const int*)d_in[2];
    const float* w    = (const float*)d_in[3];
    const float* emb  = (const float*)d_in[4];
    const float* W1   = (const float*)d_in[5];
    const float* W2   = (const float*)d_in[6];
    const float* b2   = (const float*)d_in[7];
    const float* Wh1  = (const float*)d_in[8];
    const float* bh1  = (const float*)d_in[9];
    const float* Wh2  = (const float*)d_in[10];
    const float* bh2  = (const float*)d_in[11];
    float* out = (float*)d_out;

    __nv_bfloat16 *hAh, *hAl, *hBh, *hBl, *nh, *nl;
    __nv_bfloat16 *w1h, *w1l, *w2h, *w2l, *wh1h, *wh1l;
    float *P, *inv;
    int *degi, *rowptr, *cursor;
    float4* erec;
    cudaGetSymbolAddress((void**)&hAh, g_hA_hi);
    cudaGetSymbolAddress((void**)&hAl, g_hA_lo);
    cudaGetSymbolAddress((void**)&hBh, g_hB_hi);
    cudaGetSymbolAddress((void**)&hBl, g_hB_lo);
    cudaGetSymbolAddress((void**)&nh,  g_nh);
    cudaGetSymbolAddress((void**)&nl,  g_nl);
    cudaGetSymbolAddress((void**)&P,   g_P);
    cudaGetSymbolAddress((void**)&inv, g_inv);
    cudaGetSymbolAddress((void**)&degi, g_degi);
    cudaGetSymbolAddress((void**)&rowptr, g_rowptr);
    cudaGetSymbolAddress((void**)&cursor, g_cursor);
    cudaGetSymbolAddress((void**)&erec, g_erec);
    cudaGetSymbolAddress((void**)&w1h, g_w1h);
    cudaGetSymbolAddress((void**)&w1l, g_w1l);
    cudaGetSymbolAddress((void**)&w2h, g_w2h);
    cudaGetSymbolAddress((void**)&w2l, g_w2l);
    cudaGetSymbolAddress((void**)&wh1h, g_wh1h);
    cudaGetSymbolAddress((void**)&wh1l, g_wh1l);

    cudaFuncSetAttribute(mma_gemm, cudaFuncAttributeMaxDynamicSharedMemorySize, GEMM_SMEM);

    const int T = 256;
    // CSR build (amortized over 6 layers)
    zero_kernel<<<32, T>>>((float4*)degi, NN / 4);
    hist_kernel<<<(EE + T - 1) / T, T>>>(dst, degi);
    scan_kernel<<<1, 1024>>>(degi, rowptr, cursor, inv);
    fill_kernel<<<(EE + T - 1) / T, T>>>(src, dst, w, cursor, erec);

    // weight splits
    for (int l = 0; l < NL; l++) {
        convw_kernel<<<64, T>>>(W1 + (size_t)l * HH * LDW1, LDW1, HH * HH, HH,
                                w1h + (size_t)l * HH * HH, w1l + (size_t)l * HH * HH);
        convw_kernel<<<128, T>>>(W2 + (size_t)l * HH * 512, 512, HH * 512, 512,
                                 w2h + (size_t)l * HH * 512, w2l + (size_t)l * HH * 512);
    }
    convw_kernel<<<64, T>>>(Wh1, HH, HH * HH, HH, wh1h, wh1l);

    init_h2_kernel<<<2048, T>>>(gate, emb, hAh, hAl);

    dim3 gg((NN + 127) / 128, 2);
    __nv_bfloat16 *ih = hAh, *il = hAl, *oh = hBh, *ol = hBl;
    for (int l = 0; l < NL; l++) {
        // P = h @ W1a^T (fp32, no act)
        mma_gemm<<<gg, 256, GEMM_SMEM>>>(ih, il, nullptr, nullptr,
                                         w1h + (size_t)l * HH * HH, w1l + (size_t)l * HH * HH,
                                         256, nullptr, 0, P, nullptr, nullptr, NN);
        // hN = mean_in-edges leaky(P[src] + w@W1b^T) -> bf16 hi/lo
        gather_kernel<<<1184, 256>>>(rowptr, degi, erec, W1 + (size_t)l * HH * LDW1,
                                     P, inv, nh, nl);
        // h' = relu([h | hN] @ W2^T + b2) -> bf16 pair (ping-pong)
        mma_gemm<<<gg, 256, GEMM_SMEM>>>(ih, il, nh, nl,
                                         w2h + (size_t)l * HH * 512, w2l + (size_t)l * HH * 512,
                                         512, b2 + (size_t)l * HH, 1, nullptr, oh, ol, NN);
        __nv_bfloat16* tp;
        tp = ih; ih = oh; oh = tp;
        tp = il; il = ol; ol = tp;
    }
    // head
    mma_gemm<<<gg, 256, GEMM_SMEM>>>(ih, il, nullptr, nullptr, wh1h, wh1l,
                                     256, bh1, 2, P, nullptr, nullptr, NN);
    out_kernel<<<1184, 256>>>(P, Wh2, bh2, out);
}

// round 7
// speedup vs baseline: 2.5778x; 1.0135x over previous
#include <cuda_runtime.h>
#include <cuda_bf16.h>
#include <cstddef>
#include <cstdint>

#define NN 100000
#define EE 800000
#define HH 256
#define NL 6
#define LDW1 259

// ---------------- scratch (device globals; no allocation anywhere) -------------
__device__ __align__(16) __nv_bfloat16 g_hA_hi[(size_t)NN * HH];
__device__ __align__(16) __nv_bfloat16 g_hA_lo[(size_t)NN * HH];
__device__ __align__(16) __nv_bfloat16 g_hB_hi[(size_t)NN * HH];
__device__ __align__(16) __nv_bfloat16 g_hB_lo[(size_t)NN * HH];
__device__ __align__(16) __nv_bfloat16 g_nh[(size_t)NN * HH];
__device__ __align__(16) __nv_bfloat16 g_nl[(size_t)NN * HH];
__device__ __align__(16) float g_P [(size_t)NN * HH];
__device__ float g_inv[NN];
__device__ int   g_degi[NN];
__device__ int   g_rowptr[NN];
__device__ int   g_cursor[NN];
__device__ __align__(16) float4 g_erec[EE];
__device__ __align__(16) __nv_bfloat16 g_w1h[NL * HH * HH],  g_w1l[NL * HH * HH];
__device__ __align__(16) __nv_bfloat16 g_w2h[NL * HH * 512], g_w2l[NL * HH * 512];
__device__ __align__(16) __nv_bfloat16 g_wh1h[HH * HH],      g_wh1l[HH * HH];

// ---------------- helpers ------------------------------------------------------
__device__ __forceinline__ uint32_t smem_u32(const void* p) {
    uint32_t a;
    asm("{ .reg .u64 t; cvta.to.shared.u64 t, %1; cvt.u32.u64 %0, t; }" : "=r"(a) : "l"(p));
    return a;
}
__device__ __forceinline__ uint32_t swz(uint32_t o) { return o ^ ((o >> 3) & 0x70); }

__device__ __forceinline__ void split_bf16(float f, unsigned short& h, unsigned short& l) {
    __nv_bfloat16 hb = __float2bfloat16_rn(f);
    __nv_bfloat16 lb = __float2bfloat16_rn(f - __bfloat162float(hb));
    h = __bfloat16_as_ushort(hb);
    l = __bfloat16_as_ushort(lb);
}
__device__ __forceinline__ void ldsm4(uint32_t* r, uint32_t addr) {
    asm volatile("ldmatrix.sync.aligned.m8n8.x4.shared.b16 {%0,%1,%2,%3}, [%4];"
                 : "=r"(r[0]), "=r"(r[1]), "=r"(r[2]), "=r"(r[3]) : "r"(addr));
}
__device__ __forceinline__ void mma16816(float* c, const uint32_t* a, uint32_t b0, uint32_t b1) {
    asm volatile("mma.sync.aligned.m16n8k16.row.col.f32.bf16.bf16.f32 "
                 "{%0,%1,%2,%3}, {%4,%5,%6,%7}, {%8,%9}, {%0,%1,%2,%3};"
                 : "+f"(c[0]), "+f"(c[1]), "+f"(c[2]), "+f"(c[3])
                 : "r"(a[0]), "r"(a[1]), "r"(a[2]), "r"(a[3]), "r"(b0), "r"(b1));
}
__device__ __forceinline__ void cp16(uint32_t dst, const void* src) {
    asm volatile("cp.async.cg.shared.global [%0], [%1], 16;" :: "r"(dst), "l"(src));
}
__device__ __forceinline__ void cp16z(uint32_t dst, const void* src, int sz) {
    asm volatile("cp.async.cg.shared.global [%0], [%1], 16, %2;" :: "r"(dst), "l"(src), "r"(sz));
}
__device__ __forceinline__ void cp_commit() {
    asm volatile("cp.async.commit_group;" ::: "memory");
}
template <int N> __device__ __forceinline__ void cp_wait() {
    asm volatile("cp.async.wait_group %0;" :: "n"(N) : "memory");
}

// ---------------- utility / CSR-build kernels ----------------------------------
__global__ void zero_kernel(float4* __restrict__ p, int n4) {
    int i = blockIdx.x * blockDim.x + threadIdx.x;
    int st = gridDim.x * blockDim.x;
    float4 z = make_float4(0.f, 0.f, 0.f, 0.f);
    for (; i < n4; i += st) p[i] = z;
}
__global__ void hist_kernel(const int* __restrict__ dst, int* __restrict__ degi) {
    int i = blockIdx.x * blockDim.x + threadIdx.x;
    if (i < EE) atomicAdd(&degi[dst[i]], 1);
}
__global__ __launch_bounds__(1024)
void scan_kernel(const int* __restrict__ degi, int* __restrict__ rowptr,
                 int* __restrict__ cursor, float* __restrict__ inv) {
    __shared__ int part[1024];
    const int t = threadIdx.x;
    const int CH = (NN + 1023) / 1024;
    const int start = t * CH;
    int s = 0;
    for (int i = 0; i < CH; i++) {
        int idx = start + i;
        if (idx < NN) s += degi[idx];
    }
    part[t] = s;
    __syncthreads();
    for (int off = 1; off < 1024; off <<= 1) {
        int v = part[t];
        int u = (t >= off) ? part[t - off] : 0;
        __syncthreads();
        part[t] = v + u;
        __syncthreads();
    }
    int base = (t == 0) ? 0 : part[t - 1];
    for (int i = 0; i < CH; i++) {
        int idx = start + i;
        if (idx < NN) {
            rowptr[idx] = base;
            cursor[idx] = base;
            inv[idx] = 1.0f / fmaxf((float)degi[idx], 1.0f);
            base += degi[idx];
        }
    }
}
__global__ void fill_kernel(const int* __restrict__ src, const int* __restrict__ dst,
                            const float* __restrict__ w, int* __restrict__ cursor,
                            float4* __restrict__ erec) {
    int i = blockIdx.x * blockDim.x + threadIdx.x;
    if (i < EE) {
        int pos = atomicAdd(&cursor[dst[i]], 1);
        erec[pos] = make_float4(__int_as_float(src[i]),
                                w[(size_t)i * 3 + 0], w[(size_t)i * 3 + 1], w[(size_t)i * 3 + 2]);
    }
}
__global__ void convw_kernel(const float* __restrict__ src, int ld, int n, int cols,
                             __nv_bfloat16* __restrict__ hi, __nv_bfloat16* __restrict__ lo) {
    int i = blockIdx.x * blockDim.x + threadIdx.x;
    int st = gridDim.x * blockDim.x;
    for (; i < n; i += st) {
        int r = i / cols, c = i - r * cols;
        float v = src[(size_t)r * ld + c];
        unsigned short h, l;
        split_bf16(v, h, l);
        hi[i] = __ushort_as_bfloat16(h);
        lo[i] = __ushort_as_bfloat16(l);
    }
}
__global__ void init_h2_kernel(const int* __restrict__ gt, const float* __restrict__ emb,
                               __nv_bfloat16* __restrict__ hi, __nv_bfloat16* __restrict__ lo) {
    int i = blockIdx.x * blockDim.x + threadIdx.x;
    int st = gridDim.x * blockDim.x;
    const int n = NN * HH;
    for (; i < n; i += st) {
        int nd = i >> 8, c = i & 255;
        float v = emb[(size_t)gt[nd] * HH + c];
        unsigned short h, l;
        split_bf16(v, h, l);
        hi[i] = __ushort_as_bfloat16(h);
        lo[i] = __ushort_as_bfloat16(l);
    }
}

// ---------------- CSR gather: hN = mean over in-edges of leaky(P[src] + w@W1b^T)
__global__ __launch_bounds__(256)
void gather_kernel(const int* __restrict__ rowptr, const int* __restrict__ degi,
                   const float4* __restrict__ erec, const float* __restrict__ W1f,
                   const float* __restrict__ P, const float* __restrict__ inv,
                   __nv_bfloat16* __restrict__ nh, __nv_bfloat16* __restrict__ nl) {
    const int lane = threadIdx.x & 31;
    const int wid = (blockIdx.x * blockDim.x + threadIdx.x) >> 5;
    const int nw = (gridDim.x * blockDim.x) >> 5;

    float wb[8][3];
#pragma unroll
    for (int j = 0; j < 8; j++) {
        const float* p = &W1f[(size_t)(lane * 8 + j) * LDW1 + 256];
        wb[j][0] = p[0]; wb[j][1] = p[1]; wb[j][2] = p[2];
    }
    for (int n = wid; n < NN; n += nw) {
        const int beg = rowptr[n];
        const int cnt = degi[n];
        float acc[8] = {0.f, 0.f, 0.f, 0.f, 0.f, 0.f, 0.f, 0.f};
        for (int e = 0; e < cnt; e++) {
            float4 r = __ldg(&erec[beg + e]);
            int s = __float_as_int(r.x);
            const float4* pp = (const float4*)(P + (size_t)s * HH + lane * 8);
            float4 p0 = pp[0], p1 = pp[1];
            float pv[8] = {p0.x, p0.y, p0.z, p0.w, p1.x, p1.y, p1.z, p1.w};
#pragma unroll
            for (int j = 0; j < 8; j++) {
                float t = pv[j] + r.y * wb[j][0] + r.z * wb[j][1] + r.w * wb[j][2];
                acc[j] += (t > 0.f) ? t : 0.01f * t;
            }
        }
        const float sc = inv[n];
        unsigned short hs[8], ls[8];
#pragma unroll
        for (int j = 0; j < 8; j++) split_bf16(acc[j] * sc, hs[j], ls[j]);
        uint4 vh = make_uint4((uint32_t)hs[0] | ((uint32_t)hs[1] << 16),
                              (uint32_t)hs[2] | ((uint32_t)hs[3] << 16),
                              (uint32_t)hs[4] | ((uint32_t)hs[5] << 16),
                              (uint32_t)hs[6] | ((uint32_t)hs[7] << 16));
        uint4 vl = make_uint4((uint32_t)ls[0] | ((uint32_t)ls[1] << 16),
                              (uint32_t)ls[2] | ((uint32_t)ls[3] << 16),
                              (uint32_t)ls[4] | ((uint32_t)ls[5] << 16),
                              (uint32_t)ls[6] | ((uint32_t)ls[7] << 16));
        *(uint4*)(nh + (size_t)n * HH + lane * 8) = vh;
        *(uint4*)(nl + (size_t)n * HH + lane * 8) = vl;
    }
}

// ---------------- mma.sync GEMM (term-major MMA issue order) --------------------
#define GEMM_SMEM 131072

__global__ __launch_bounds__(256, 1)
void mma_gemm(const __nv_bfloat16* __restrict__ aH1, const __nv_bfloat16* __restrict__ aL1,
              const __nv_bfloat16* __restrict__ aH2, const __nv_bfloat16* __restrict__ aL2,
              const __nv_bfloat16* __restrict__ bH, const __nv_bfloat16* __restrict__ bL,
              int K, const float* __restrict__ bias, int mode,
              float* __restrict__ outF, __nv_bfloat16* __restrict__ oH,
              __nv_bfloat16* __restrict__ oL, int M) {
    extern __shared__ char smem[];
    const uint32_t sbase = smem_u32(smem);
    const int t = threadIdx.x;
    const int m0 = blockIdx.x * 128;
    const int n0 = blockIdx.y * 128;
    const int C = K >> 6;
    const int w = t >> 5, lane = t & 31;
    const int wm = w & 3, wn = w >> 2;

    float acc[2][8][4];
#pragma unroll
    for (int a = 0; a < 2; a++)
#pragma unroll
        for (int b = 0; b < 8; b++)
#pragma unroll
            for (int c = 0; c < 4; c++) acc[a][b][c] = 0.f;

    auto issue_stage = [&](int c) {
        const uint32_t st = sbase + (uint32_t)(c & 1) * 65536u;
        const int kc = c << 6;
        const __nv_bfloat16* AH = (kc < 256) ? aH1 : aH2;
        const __nv_bfloat16* AL = (kc < 256) ? aL1 : aL2;
        const int ko = kc & 255;
        for (int s = t; s < 2048; s += 256) {
            int which = s >> 10, ss = s & 1023;
            int r = ss >> 3, c8 = ss & 7;
            int gr = m0 + r;
            int grc = gr < M ? gr : (M - 1);
            const __nv_bfloat16* gp = (which ? AL : AH) + ((size_t)grc * HH + ko + c8 * 8);
            uint32_t dst = st + (uint32_t)which * 16384u + swz((uint32_t)(r * 128 + c8 * 16));
            cp16z(dst, gp, gr < M ? 16 : 0);
        }
        for (int s = t; s < 2048; s += 256) {
            int which = s >> 10, ss = s & 1023;
            int n = ss >> 3, c8 = ss & 7;
            const __nv_bfloat16* gp = (which ? bL : bH) + ((size_t)(n0 + n) * K + kc + c8 * 8);
            uint32_t dst = st + 32768u + (uint32_t)which * 16384u + swz((uint32_t)(n * 128 + c8 * 16));
            cp16(dst, gp);
        }
    };

    auto compute = [&](int b) {
        const uint32_t Ab = sbase + (uint32_t)b * 65536u;
        const uint32_t Bb = Ab + 32768u;
        const int sub = lane >> 3, rr = lane & 7;
#pragma unroll
        for (int ks = 0; ks < 4; ks++) {
            const int kb = ks * 32;
            // ---- load ALL fragments for this k16 step first
            uint32_t Ah[2][4], Al[2][4];
#pragma unroll
            for (int mt = 0; mt < 2; mt++) {
                int row = wm * 32 + mt * 16 + (sub & 1) * 8 + rr;
                uint32_t off = swz((uint32_t)(row * 128 + kb + (sub >> 1) * 16));
                ldsm4(Ah[mt], Ab + off);
                ldsm4(Al[mt], Ab + 16384u + off);
            }
            uint32_t Bh[4][4], Bl[4][4];
#pragma unroll
            for (int np = 0; np < 4; np++) {
                int nrow = wn * 64 + np * 16 + (sub >> 1) * 8 + rr;
                uint32_t off = swz((uint32_t)(nrow * 128 + kb + (sub & 1) * 16));
                ldsm4(Bh[np], Bb + off);
                ldsm4(Bl[np], Bb + 16384u + off);
            }
            // ---- term-major issue: same-acc reuse distance = 16 MMAs
#pragma unroll
            for (int np = 0; np < 4; np++)
#pragma unroll
                for (int mt = 0; mt < 2; mt++) {
                    mma16816(acc[mt][2 * np],     Ah[mt], Bh[np][0], Bh[np][1]);
                    mma16816(acc[mt][2 * np + 1], Ah[mt], Bh[np][2], Bh[np][3]);
                }
#pragma unroll
            for (int np = 0; np < 4; np++)
#pragma unroll
                for (int mt = 0; mt < 2; mt++) {
                    mma16816(acc[mt][2 * np],     Ah[mt], Bl[np][0], Bl[np][1]);
                    mma16816(acc[mt][2 * np + 1], Ah[mt], Bl[np][2], Bl[np][3]);
                }
#pragma unroll
            for (int np = 0; np < 4; np++)
#pragma unroll
                for (int mt = 0; mt < 2; mt++) {
                    mma16816(acc[mt][2 * np],     Al[mt], Bh[np][0], Bh[np][1]);
                    mma16816(acc[mt][2 * np + 1], Al[mt], Bh[np][2], Bh[np][3]);
                }
        }
    };

    issue_stage(0);
    cp_commit();
    for (int c = 0; c < C; c++) {
        if (c + 1 < C) { issue_stage(c + 1); cp_commit(); }
        if (c + 1 < C) cp_wait<1>(); else cp_wait<0>();
        __syncthreads();
        compute(c & 1);
        __syncthreads();
    }

    const int q = lane >> 2;
    const int r2 = (lane & 3) * 2;
#pragma unroll
    for (int mt = 0; mt < 2; mt++) {
        int row0 = m0 + wm * 32 + mt * 16 + q;
#pragma unroll
        for (int half = 0; half < 2; half++) {
            int row = row0 + half * 8;
            if (row >= M) continue;
#pragma unroll
            for (int nt = 0; nt < 8; nt++) {
                int gc = n0 + wn * 64 + nt * 8 + r2;
                float v0 = acc[mt][nt][half * 2 + 0];
                float v1 = acc[mt][nt][half * 2 + 1];
                if (mode) {
                    v0 = fmaxf(v0 + __ldg(&bias[gc]), 0.f);
                    v1 = fmaxf(v1 + __ldg(&bias[gc + 1]), 0.f);
                }
                if (mode == 1) {
                    unsigned short h0, l0, h1, l1;
                    split_bf16(v0, h0, l0);
                    split_bf16(v1, h1, l1);
                    *(uint32_t*)(oH + (size_t)row * HH + gc) = (uint32_t)h0 | ((uint32_t)h1 << 16);
                    *(uint32_t*)(oL + (size_t)row * HH + gc) = (uint32_t)l0 | ((uint32_t)l1 << 16);
                } else {
                    *(float2*)(outF + (size_t)row * HH + gc) = make_float2(v0, v1);
                }
            }
        }
    }
}

// ---------------- final head dot -----------------------------------------------
__global__ __launch_bounds__(256)
void out_kernel(const float* __restrict__ x, const float* __restrict__ Wh2,
                const float* __restrict__ bh2, float* __restrict__ out) {
    const int lane = threadIdx.x & 31;
    const int wid = (blockIdx.x * blockDim.x + threadIdx.x) >> 5;
    const int nw = (gridDim.x * blockDim.x) >> 5;
    float4 wr0 = *(const float4*)&Wh2[lane * 8];
    float4 wr1 = *(const float4*)&Wh2[lane * 8 + 4];
    float b = bh2[0];
    for (int n = wid; n < NN; n += nw) {
        const float4* xp = (const float4*)(x + (size_t)n * HH + lane * 8);
        float4 x0 = xp[0], x1 = xp[1];
        float s = x0.x * wr0.x + x0.y * wr0.y + x0.z * wr0.z + x0.w * wr0.w
                + x1.x * wr1.x + x1.y * wr1.y + x1.z * wr1.z + x1.w * wr1.w;
#pragma unroll
        for (int o = 16; o > 0; o >>= 1) s += __shfl_xor_sync(0xffffffffu, s, o);
        if (lane == 0) out[n] = s + b;
    }
}

// ---------------- launcher ------------------------------------------------------
extern "C" void kernel_launch(void* const* d_in, const int* in_sizes, int n_in,
                              void* d_out, int out_size) {
    const int*   gate = (const int*)d_in[0];
    const int*   src  = (const int*)d_in[1];
    const int*   dst  = (const int*)d_in[2];
    const float* w    = (const float*)d_in[3];
    const float* emb  = (const float*)d_in[4];
    const float* W1   = (const float*)d_in[5];
    const float* W2   = (const float*)d_in[6];
    const float* b2   = (const float*)d_in[7];
    const float* Wh1  = (const float*)d_in[8];
    const float* bh1  = (const float*)d_in[9];
    const float* Wh2  = (const float*)d_in[10];
    const float* bh2  = (const float*)d_in[11];
    float* out = (float*)d_out;

    __nv_bfloat16 *hAh, *hAl, *hBh, *hBl, *nh, *nl;
    __nv_bfloat16 *w1h, *w1l, *w2h, *w2l, *wh1h, *wh1l;
    float *P, *inv;
    int *degi, *rowptr, *cursor;
    float4* erec;
    cudaGetSymbolAddress((void**)&hAh, g_hA_hi);
    cudaGetSymbolAddress((void**)&hAl, g_hA_lo);
    cudaGetSymbolAddress((void**)&hBh, g_hB_hi);
    cudaGetSymbolAddress((void**)&hBl, g_hB_lo);
    cudaGetSymbolAddress((void**)&nh,  g_nh);
    cudaGetSymbolAddress((void**)&nl,  g_nl);
    cudaGetSymbolAddress((void**)&P,   g_P);
    cudaGetSymbolAddress((void**)&inv, g_inv);
    cudaGetSymbolAddress((void**)&degi, g_degi);
    cudaGetSymbolAddress((void**)&rowptr, g_rowptr);
    cudaGetSymbolAddress((void**)&cursor, g_cursor);
    cudaGetSymbolAddress((void**)&erec, g_erec);
    cudaGetSymbolAddress((void**)&w1h, g_w1h);
    cudaGetSymbolAddress((void**)&w1l, g_w1l);
    cudaGetSymbolAddress((void**)&w2h, g_w2h);
    cudaGetSymbolAddress((void**)&w2l, g_w2l);
    cudaGetSymbolAddress((void**)&wh1h, g_wh1h);
    cudaGetSymbolAddress((void**)&wh1l, g_wh1l);

    cudaFuncSetAttribute(mma_gemm, cudaFuncAttributeMaxDynamicSharedMemorySize, GEMM_SMEM);

    const int T = 256;
    zero_kernel<<<32, T>>>((float4*)degi, NN / 4);
    hist_kernel<<<(EE + T - 1) / T, T>>>(dst, degi);
    scan_kernel<<<1, 1024>>>(degi, rowptr, cursor, inv);
    fill_kernel<<<(EE + T - 1) / T, T>>>(src, dst, w, cursor, erec);

    for (int l = 0; l < NL; l++) {
        convw_kernel<<<64, T>>>(W1 + (size_t)l * HH * LDW1, LDW1, HH * HH, HH,
                                w1h + (size_t)l * HH * HH, w1l + (size_t)l * HH * HH);
        convw_kernel<<<128, T>>>(W2 + (size_t)l * HH * 512, 512, HH * 512, 512,
                                 w2h + (size_t)l * HH * 512, w2l + (size_t)l * HH * 512);
    }
    convw_kernel<<<64, T>>>(Wh1, HH, HH * HH, HH, wh1h, wh1l);

    init_h2_kernel<<<2048, T>>>(gate, emb, hAh, hAl);

    dim3 gg((NN + 127) / 128, 2);
    __nv_bfloat16 *ih = hAh, *il = hAl, *oh = hBh, *ol = hBl;
    for (int l = 0; l < NL; l++) {
        mma_gemm<<<gg, 256, GEMM_SMEM>>>(ih, il, nullptr, nullptr,
                                         w1h + (size_t)l * HH * HH, w1l + (size_t)l * HH * HH,
                                         256, nullptr, 0, P, nullptr, nullptr, NN);
        gather_kernel<<<1184, 256>>>(rowptr, degi, erec, W1 + (size_t)l * HH * LDW1,
                                     P, inv, nh, nl);
        mma_gemm<<<gg, 256, GEMM_SMEM>>>(ih, il, nh, nl,
                                         w2h + (size_t)l * HH * 512, w2l + (size_t)l * HH * 512,
                                         512, b2 + (size_t)l * HH, 1, nullptr, oh, ol, NN);
        __nv_bfloat16* tp;
        tp = ih; ih = oh; oh = tp;
        tp = il; il = ol; ol = tp;
    }
    mma_gemm<<<gg, 256, GEMM_SMEM>>>(ih, il, nullptr, nullptr, wh1h, wh1l,
                                     256, bh1, 2, P, nullptr, nullptr, NN);
    out_kernel<<<1184, 256>>>(P, Wh2, bh2, out);
}

// round 9
// speedup vs baseline: 2.7059x; 1.0497x over previous
#include <cuda_runtime.h>
#include <cuda_bf16.h>
#include <cstddef>
#include <cstdint>

#define NN 100000
#define EE 800000
#define HH 256
#define NL 6
#define LDW1 259

// ---------------- scratch (device globals; no allocation anywhere) -------------
__device__ __align__(16) __nv_bfloat16 g_hA_hi[(size_t)NN * HH];
__device__ __align__(16) __nv_bfloat16 g_hA_lo[(size_t)NN * HH];
__device__ __align__(16) __nv_bfloat16 g_hB_hi[(size_t)NN * HH];
__device__ __align__(16) __nv_bfloat16 g_hB_lo[(size_t)NN * HH];
__device__ __align__(16) __nv_bfloat16 g_nh[(size_t)NN * HH];
__device__ __align__(16) __nv_bfloat16 g_nl[(size_t)NN * HH];
__device__ __align__(16) float g_P [(size_t)NN * HH];
__device__ float g_inv[NN];
__device__ int   g_degi[NN];
__device__ int   g_rowptr[NN];
__device__ int   g_cursor[NN];
__device__ __align__(16) float4 g_erec[EE];
__device__ __align__(16) __nv_bfloat16 g_w1h[NL * HH * HH],  g_w1l[NL * HH * HH];
__device__ __align__(16) __nv_bfloat16 g_w2h[NL * HH * 512], g_w2l[NL * HH * 512];
__device__ __align__(16) __nv_bfloat16 g_wh1h[HH * HH],      g_wh1l[HH * HH];

// ---------------- helpers ------------------------------------------------------
__device__ __forceinline__ uint32_t smem_u32(const void* p) {
    uint32_t a;
    asm("{ .reg .u64 t; cvta.to.shared.u64 t, %1; cvt.u32.u64 %0, t; }" : "=r"(a) : "l"(p));
    return a;
}
// SW64 swizzle for 64-byte rows: 16B-unit index (bits[5:4]) ^= row[2:1] (bits[8:7])
__device__ __forceinline__ uint32_t swz64(uint32_t o) { return o ^ ((o >> 3) & 0x30); }

__device__ __forceinline__ void split_bf16(float f, unsigned short& h, unsigned short& l) {
    __nv_bfloat16 hb = __float2bfloat16_rn(f);
    __nv_bfloat16 lb = __float2bfloat16_rn(f - __bfloat162float(hb));
    h = __bfloat16_as_ushort(hb);
    l = __bfloat16_as_ushort(lb);
}
__device__ __forceinline__ void ldsm4(uint32_t* r, uint32_t addr) {
    asm volatile("ldmatrix.sync.aligned.m8n8.x4.shared.b16 {%0,%1,%2,%3}, [%4];"
                 : "=r"(r[0]), "=r"(r[1]), "=r"(r[2]), "=r"(r[3]) : "r"(addr));
}
__device__ __forceinline__ void mma16816(float* c, const uint32_t* a, uint32_t b0, uint32_t b1) {
    asm volatile("mma.sync.aligned.m16n8k16.row.col.f32.bf16.bf16.f32 "
                 "{%0,%1,%2,%3}, {%4,%5,%6,%7}, {%8,%9}, {%0,%1,%2,%3};"
                 : "+f"(c[0]), "+f"(c[1]), "+f"(c[2]), "+f"(c[3])
                 : "r"(a[0]), "r"(a[1]), "r"(a[2]), "r"(a[3]), "r"(b0), "r"(b1));
}
__device__ __forceinline__ void cp16(uint32_t dst, const void* src) {
    asm volatile("cp.async.cg.shared.global [%0], [%1], 16;" :: "r"(dst), "l"(src));
}
__device__ __forceinline__ void cp16z(uint32_t dst, const void* src, int sz) {
    asm volatile("cp.async.cg.shared.global [%0], [%1], 16, %2;" :: "r"(dst), "l"(src), "r"(sz));
}
__device__ __forceinline__ void cp_commit() {
    asm volatile("cp.async.commit_group;" ::: "memory");
}
template <int N> __device__ __forceinline__ void cp_wait() {
    asm volatile("cp.async.wait_group %0;" :: "n"(N) : "memory");
}

// ---------------- utility / CSR-build kernels ----------------------------------
__global__ void zero_kernel(float4* __restrict__ p, int n4) {
    int i = blockIdx.x * blockDim.x + threadIdx.x;
    int st = gridDim.x * blockDim.x;
    float4 z = make_float4(0.f, 0.f, 0.f, 0.f);
    for (; i < n4; i += st) p[i] = z;
}
__global__ void hist_kernel(const int* __restrict__ dst, int* __restrict__ degi) {
    int i = blockIdx.x * blockDim.x + threadIdx.x;
    if (i < EE) atomicAdd(&degi[dst[i]], 1);
}
__global__ __launch_bounds__(1024)
void scan_kernel(const int* __restrict__ degi, int* __restrict__ rowptr,
                 int* __restrict__ cursor, float* __restrict__ inv) {
    __shared__ int part[1024];
    const int t = threadIdx.x;
    const int CH = (NN + 1023) / 1024;
    const int start = t * CH;
    int s = 0;
    for (int i = 0; i < CH; i++) {
        int idx = start + i;
        if (idx < NN) s += degi[idx];
    }
    part[t] = s;
    __syncthreads();
    for (int off = 1; off < 1024; off <<= 1) {
        int v = part[t];
        int u = (t >= off) ? part[t - off] : 0;
        __syncthreads();
        part[t] = v + u;
        __syncthreads();
    }
    int base = (t == 0) ? 0 : part[t - 1];
    for (int i = 0; i < CH; i++) {
        int idx = start + i;
        if (idx < NN) {
            rowptr[idx] = base;
            cursor[idx] = base;
            inv[idx] = 1.0f / fmaxf((float)degi[idx], 1.0f);
            base += degi[idx];
        }
    }
}
__global__ void fill_kernel(const int* __restrict__ src, const int* __restrict__ dst,
                            const float* __restrict__ w, int* __restrict__ cursor,
                            float4* __restrict__ erec) {
    int i = blockIdx.x * blockDim.x + threadIdx.x;
    if (i < EE) {
        int pos = atomicAdd(&cursor[dst[i]], 1);
        erec[pos] = make_float4(__int_as_float(src[i]),
                                w[(size_t)i * 3 + 0], w[(size_t)i * 3 + 1], w[(size_t)i * 3 + 2]);
    }
}
__global__ void convw_kernel(const float* __restrict__ src, int ld, int n, int cols,
                             __nv_bfloat16* __restrict__ hi, __nv_bfloat16* __restrict__ lo) {
    int i = blockIdx.x * blockDim.x + threadIdx.x;
    int st = gridDim.x * blockDim.x;
    for (; i < n; i += st) {
        int r = i / cols, c = i - r * cols;
        float v = src[(size_t)r * ld + c];
        unsigned short h, l;
        split_bf16(v, h, l);
        hi[i] = __ushort_as_bfloat16(h);
        lo[i] = __ushort_as_bfloat16(l);
    }
}
__global__ void init_h2_kernel(const int* __restrict__ gt, const float* __restrict__ emb,
                               __nv_bfloat16* __restrict__ hi, __nv_bfloat16* __restrict__ lo) {
    int i = blockIdx.x * blockDim.x + threadIdx.x;
    int st = gridDim.x * blockDim.x;
    const int n = NN * HH;
    for (; i < n; i += st) {
        int nd = i >> 8, c = i & 255;
        float v = emb[(size_t)gt[nd] * HH + c];
        unsigned short h, l;
        split_bf16(v, h, l);
        hi[i] = __ushort_as_bfloat16(h);
        lo[i] = __ushort_as_bfloat16(l);
    }
}

// ---------------- CSR gather: hN = mean over in-edges of leaky(P[src] + w@W1b^T)
__global__ __launch_bounds__(256)
void gather_kernel(const int* __restrict__ rowptr, const int* __restrict__ degi,
                   const float4* __restrict__ erec, const float* __restrict__ W1f,
                   const float* __restrict__ P, const float* __restrict__ inv,
                   __nv_bfloat16* __restrict__ nh, __nv_bfloat16* __restrict__ nl) {
    const int lane = threadIdx.x & 31;
    const int wid = (blockIdx.x * blockDim.x + threadIdx.x) >> 5;
    const int nw = (gridDim.x * blockDim.x) >> 5;

    float wb[8][3];
#pragma unroll
    for (int j = 0; j < 8; j++) {
        const float* p = &W1f[(size_t)(lane * 8 + j) * LDW1 + 256];
        wb[j][0] = p[0]; wb[j][1] = p[1]; wb[j][2] = p[2];
    }
    for (int n = wid; n < NN; n += nw) {
        const int beg = rowptr[n];
        const int cnt = degi[n];
        float acc[8] = {0.f, 0.f, 0.f, 0.f, 0.f, 0.f, 0.f, 0.f};
        for (int e = 0; e < cnt; e++) {
            float4 r = __ldg(&erec[beg + e]);
            int s = __float_as_int(r.x);
            const float4* pp = (const float4*)(P + (size_t)s * HH + lane * 8);
            float4 p0 = pp[0], p1 = pp[1];
            float pv[8] = {p0.x, p0.y, p0.z, p0.w, p1.x, p1.y, p1.z, p1.w};
#pragma unroll
            for (int j = 0; j < 8; j++) {
                float t = pv[j] + r.y * wb[j][0] + r.z * wb[j][1] + r.w * wb[j][2];
                acc[j] += (t > 0.f) ? t : 0.01f * t;
            }
        }
        const float sc = inv[n];
        unsigned short hs[8], ls[8];
#pragma unroll
        for (int j = 0; j < 8; j++) split_bf16(acc[j] * sc, hs[j], ls[j]);
        uint4 vh = make_uint4((uint32_t)hs[0] | ((uint32_t)hs[1] << 16),
                              (uint32_t)hs[2] | ((uint32_t)hs[3] << 16),
                              (uint32_t)hs[4] | ((uint32_t)hs[5] << 16),
                              (uint32_t)hs[6] | ((uint32_t)hs[7] << 16));
        uint4 vl = make_uint4((uint32_t)ls[0] | ((uint32_t)ls[1] << 16),
                              (uint32_t)ls[2] | ((uint32_t)ls[3] << 16),
                              (uint32_t)ls[4] | ((uint32_t)ls[5] << 16),
                              (uint32_t)ls[6] | ((uint32_t)ls[7] << 16));
        *(uint4*)(nh + (size_t)n * HH + lane * 8) = vh;
        *(uint4*)(nl + (size_t)n * HH + lane * 8) = vl;
    }
}

// ---------------- mma.sync GEMM: BK=32, 64B rows, 2 CTAs/SM ---------------------
// Stage layout (32KB): Ah[0,8K) Al[8K,16K) Bh[16K,24K) Bl[24K,32K); 2 stages.
#define GEMM_SMEM 65536

__global__ __launch_bounds__(256, 2)
void mma_gemm(const __nv_bfloat16* __restrict__ aH1, const __nv_bfloat16* __restrict__ aL1,
              const __nv_bfloat16* __restrict__ aH2, const __nv_bfloat16* __restrict__ aL2,
              const __nv_bfloat16* __restrict__ bH, const __nv_bfloat16* __restrict__ bL,
              int K, const float* __restrict__ bias, int mode,
              float* __restrict__ outF, __nv_bfloat16* __restrict__ oH,
              __nv_bfloat16* __restrict__ oL, int M) {
    extern __shared__ char smem[];
    const uint32_t sbase = smem_u32(smem);
    const int t = threadIdx.x;
    const int m0 = blockIdx.x * 128;
    const int n0 = blockIdx.y * 128;
    const int C = K >> 5;
    const int w = t >> 5, lane = t & 31;
    const int wm = w & 3, wn = w >> 2;

    float acc[2][8][4];
#pragma unroll
    for (int a = 0; a < 2; a++)
#pragma unroll
        for (int b = 0; b < 8; b++)
#pragma unroll
            for (int c = 0; c < 4; c++) acc[a][b][c] = 0.f;

    auto issue_stage = [&](int c) {
        const uint32_t st = sbase + (uint32_t)(c & 1) * 32768u;
        const int kc = c << 5;
        const __nv_bfloat16* AH = (kc < 256) ? aH1 : aH2;
        const __nv_bfloat16* AL = (kc < 256) ? aL1 : aL2;
        const int ko = kc & 255;
        // A: 128 rows x 4 units x {hi,lo} = 1024 x 16B
        for (int s = t; s < 1024; s += 256) {
            int which = s >> 9, ss = s & 511;
            int r = ss >> 2, u = ss & 3;
            int gr = m0 + r;
            int grc = gr < M ? gr : (M - 1);
            const __nv_bfloat16* gp = (which ? AL : AH) + ((size_t)grc * HH + ko + u * 8);
            uint32_t dst = st + (uint32_t)which * 8192u + swz64((uint32_t)(r * 64 + u * 16));
            cp16z(dst, gp, gr < M ? 16 : 0);
        }
        // B: 128 rows x 4 units x {hi,lo} = 1024 x 16B
        for (int s = t; s < 1024; s += 256) {
            int which = s >> 9, ss = s & 511;
            int n = ss >> 2, u = ss & 3;
            const __nv_bfloat16* gp = (which ? bL : bH) + ((size_t)(n0 + n) * K + kc + u * 8);
            uint32_t dst = st + 16384u + (uint32_t)which * 8192u + swz64((uint32_t)(n * 64 + u * 16));
            cp16(dst, gp);
        }
    };

    auto compute = [&](int b) {
        const uint32_t Ab = sbase + (uint32_t)b * 32768u;
        const uint32_t Bb = Ab + 16384u;
        const int sub = lane >> 3, rr = lane & 7;
#pragma unroll
        for (int ks = 0; ks < 2; ks++) {
            const int kb = ks * 32;
            uint32_t Ah[2][4], Al[2][4];
#pragma unroll
            for (int mt = 0; mt < 2; mt++) {
                int row = wm * 32 + mt * 16 + (sub & 1) * 8 + rr;
                uint32_t off = swz64((uint32_t)(row * 64 + kb + (sub >> 1) * 16));
                ldsm4(Ah[mt], Ab + off);
                ldsm4(Al[mt], Ab + 8192u + off);
            }
#pragma unroll
            for (int np = 0; np < 4; np++) {
                int nrow = wn * 64 + np * 16 + (sub >> 1) * 8 + rr;
                uint32_t off = swz64((uint32_t)(nrow * 64 + kb + (sub & 1) * 16));
                uint32_t Bh[4], Bl[4];
                ldsm4(Bh, Bb + off);
                ldsm4(Bl, Bb + 8192u + off);
#pragma unroll
                for (int mt = 0; mt < 2; mt++) {
                    mma16816(acc[mt][2 * np],     Ah[mt], Bh[0], Bh[1]);
                    mma16816(acc[mt][2 * np],     Ah[mt], Bl[0], Bl[1]);
                    mma16816(acc[mt][2 * np],     Al[mt], Bh[0], Bh[1]);
                    mma16816(acc[mt][2 * np + 1], Ah[mt], Bh[2], Bh[3]);
                    mma16816(acc[mt][2 * np + 1], Ah[mt], Bl[2], Bl[3]);
                    mma16816(acc[mt][2 * np + 1], Al[mt], Bh[2], Bh[3]);
                }
            }
        }
    };

    issue_stage(0);
    cp_commit();
    for (int c = 0; c < C; c++) {
        if (c + 1 < C) { issue_stage(c + 1); cp_commit(); }
        if (c + 1 < C) cp_wait<1>(); else cp_wait<0>();
        __syncthreads();
        compute(c & 1);
        __syncthreads();
    }

    const int q = lane >> 2;
    const int r2 = (lane & 3) * 2;
#pragma unroll
    for (int mt = 0; mt < 2; mt++) {
        int row0 = m0 + wm * 32 + mt * 16 + q;
#pragma unroll
        for (int half = 0; half < 2; half++) {
            int row = row0 + half * 8;
            if (row >= M) continue;
#pragma unroll
            for (int nt = 0; nt < 8; nt++) {
                int gc = n0 + wn * 64 + nt * 8 + r2;
                float v0 = acc[mt][nt][half * 2 + 0];
                float v1 = acc[mt][nt][half * 2 + 1];
                if (mode) {
                    v0 = fmaxf(v0 + __ldg(&bias[gc]), 0.f);
                    v1 = fmaxf(v1 + __ldg(&bias[gc + 1]), 0.f);
                }
                if (mode == 1) {
                    unsigned short h0, l0, h1, l1;
                    split_bf16(v0, h0, l0);
                    split_bf16(v1, h1, l1);
                    *(uint32_t*)(oH + (size_t)row * HH + gc) = (uint32_t)h0 | ((uint32_t)h1 << 16);
                    *(uint32_t*)(oL + (size_t)row * HH + gc) = (uint32_t)l0 | ((uint32_t)l1 << 16);
                } else {
                    *(float2*)(outF + (size_t)row * HH + gc) = make_float2(v0, v1);
                }
            }
        }
    }
}

// ---------------- final head dot -----------------------------------------------
__global__ __launch_bounds__(256)
void out_kernel(const float* __restrict__ x, const float* __restrict__ Wh2,
                const float* __restrict__ bh2, float* __restrict__ out) {
    const int lane = threadIdx.x & 31;
    const int wid = (blockIdx.x * blockDim.x + threadIdx.x) >> 5;
    const int nw = (gridDim.x * blockDim.x) >> 5;
    float4 wr0 = *(const float4*)&Wh2[lane * 8];
    float4 wr1 = *(const float4*)&Wh2[lane * 8 + 4];
    float b = bh2[0];
    for (int n = wid; n < NN; n += nw) {
        const float4* xp = (const float4*)(x + (size_t)n * HH + lane * 8);
        float4 x0 = xp[0], x1 = xp[1];
        float s = x0.x * wr0.x + x0.y * wr0.y + x0.z * wr0.z + x0.w * wr0.w
                + x1.x * wr1.x + x1.y * wr1.y + x1.z * wr1.z + x1.w * wr1.w;
#pragma unroll
        for (int o = 16; o > 0; o >>= 1) s += __shfl_xor_sync(0xffffffffu, s, o);
        if (lane == 0) out[n] = s + b;
    }
}

// ---------------- launcher ------------------------------------------------------
extern "C" void kernel_launch(void* const* d_in, const int* in_sizes, int n_in,
                              void* d_out, int out_size) {
    const int*   gate = (const int*)d_in[0];
    const int*   src  = (const int*)d_in[1];
    const int*   dst  = (const int*)d_in[2];
    const float* w    = (const float*)d_in[3];
    const float* emb  = (const float*)d_in[4];
    const float* W1   = (const float*)d_in[5];
    const float* W2   = (const float*)d_in[6];
    const float* b2   = (const float*)d_in[7];
    const float* Wh1  = (const float*)d_in[8];
    const float* bh1  = (const float*)d_in[9];
    const float* Wh2  = (const float*)d_in[10];
    const float* bh2  = (const float*)d_in[11];
    float* out = (float*)d_out;

    __nv_bfloat16 *hAh, *hAl, *hBh, *hBl, *nh, *nl;
    __nv_bfloat16 *w1h, *w1l, *w2h, *w2l, *wh1h, *wh1l;
    float *P, *inv;
    int *degi, *rowptr, *cursor;
    float4* erec;
    cudaGetSymbolAddress((void**)&hAh, g_hA_hi);
    cudaGetSymbolAddress((void**)&hAl, g_hA_lo);
    cudaGetSymbolAddress((void**)&hBh, g_hB_hi);
    cudaGetSymbolAddress((void**)&hBl, g_hB_lo);
    cudaGetSymbolAddress((void**)&nh,  g_nh);
    cudaGetSymbolAddress((void**)&nl,  g_nl);
    cudaGetSymbolAddress((void**)&P,   g_P);
    cudaGetSymbolAddress((void**)&inv, g_inv);
    cudaGetSymbolAddress((void**)&degi, g_degi);
    cudaGetSymbolAddress((void**)&rowptr, g_rowptr);
    cudaGetSymbolAddress((void**)&cursor, g_cursor);
    cudaGetSymbolAddress((void**)&erec, g_erec);
    cudaGetSymbolAddress((void**)&w1h, g_w1h);
    cudaGetSymbolAddress((void**)&w1l, g_w1l);
    cudaGetSymbolAddress((void**)&w2h, g_w2h);
    cudaGetSymbolAddress((void**)&w2l, g_w2l);
    cudaGetSymbolAddress((void**)&wh1h, g_wh1h);
    cudaGetSymbolAddress((void**)&wh1l, g_wh1l);

    cudaFuncSetAttribute(mma_gemm, cudaFuncAttributeMaxDynamicSharedMemorySize, GEMM_SMEM);

    const int T = 256;
    zero_kernel<<<32, T>>>((float4*)degi, NN / 4);
    hist_kernel<<<(EE + T - 1) / T, T>>>(dst, degi);
    scan_kernel<<<1, 1024>>>(degi, rowptr, cursor, inv);
    fill_kernel<<<(EE + T - 1) / T, T>>>(src, dst, w, cursor, erec);

    for (int l = 0; l < NL; l++) {
        convw_kernel<<<64, T>>>(W1 + (size_t)l * HH * LDW1, LDW1, HH * HH, HH,
                                w1h + (size_t)l * HH * HH, w1l + (size_t)l * HH * HH);
        convw_kernel<<<128, T>>>(W2 + (size_t)l * HH * 512, 512, HH * 512, 512,
                                 w2h + (size_t)l * HH * 512, w2l + (size_t)l * HH * 512);
    }
    convw_kernel<<<64, T>>>(Wh1, HH, HH * HH, HH, wh1h, wh1l);

    init_h2_kernel<<<2048, T>>>(gate, emb, hAh, hAl);

    dim3 gg((NN + 127) / 128, 2);
    __nv_bfloat16 *ih = hAh, *il = hAl, *oh = hBh, *ol = hBl;
    for (int l = 0; l < NL; l++) {
        mma_gemm<<<gg, 256, GEMM_SMEM>>>(ih, il, nullptr, nullptr,
                                         w1h + (size_t)l * HH * HH, w1l + (size_t)l * HH * HH,
                                         256, nullptr, 0, P, nullptr, nullptr, NN);
        gather_kernel<<<1184, 256>>>(rowptr, degi, erec, W1 + (size_t)l * HH * LDW1,
                                     P, inv, nh, nl);
        mma_gemm<<<gg, 256, GEMM_SMEM>>>(ih, il, nh, nl,
                                         w2h + (size_t)l * HH * 512, w2l + (size_t)l * HH * 512,
                                         512, b2 + (size_t)l * HH, 1, nullptr, oh, ol, NN);
        __nv_bfloat16* tp;
        tp = ih; ih = oh; oh = tp;
        tp = il; il = ol; ol = tp;
    }
    mma_gemm<<<gg, 256, GEMM_SMEM>>>(ih, il, nullptr, nullptr, wh1h, wh1l,
                                     256, bh1, 2, P, nullptr, nullptr, NN);
    out_kernel<<<1184, 256>>>(P, Wh2, bh2, out);
}